// round 1
// baseline (speedup 1.0000x reference)
#include <cuda_runtime.h>

// Problem constants
#define Bdim 2
#define Tdim 2048
#define Cdim 1024
#define Hn   16
#define HDd  64
#define Mrows (Bdim * Tdim)   // 4096
#define N3    (3 * Cdim)      // 3072

// Scratch (allocation-free rule: __device__ globals), head-major [B,H,T,HD]
__device__ float g_q[Bdim * Hn * Tdim * HDd];
__device__ float g_k[Bdim * Hn * Tdim * HDd];
__device__ float g_v[Bdim * Hn * Tdim * HDd];
__device__ float g_y[Bdim * Hn * Tdim * HDd];

// ---------------------------------------------------------------------------
// Kernel 1: QKV GEMM  [4096 x 1024] @ [1024 x 3072] + bias,
// scattered to head-major g_q/g_k/g_v.
// 64x64 tile, BK=32, 256 threads, 4x4 per thread.
// ---------------------------------------------------------------------------
__global__ __launch_bounds__(256) void qkv_gemm_kernel(
    const float* __restrict__ A, const float* __restrict__ W,
    const float* __restrict__ bias)
{
    __shared__ float As[64][32];
    __shared__ float Bs[32][64];

    const int tid = threadIdx.x;
    const int tx = tid & 15;
    const int ty = tid >> 4;
    const int n0 = blockIdx.x * 64;
    const int m0 = blockIdx.y * 64;

    float acc[4][4] = {};

    for (int kt = 0; kt < Cdim / 32; ++kt) {
        #pragma unroll
        for (int it = 0; it < 2; ++it) {
            int idx = tid + it * 256;          // 512 float4 total
            int row = idx >> 3;
            int c4  = (idx & 7) << 2;
            *(float4*)&As[row][c4] =
                *(const float4*)&A[(m0 + row) * Cdim + kt * 32 + c4];
        }
        #pragma unroll
        for (int it = 0; it < 2; ++it) {
            int idx = tid + it * 256;
            int row = idx >> 4;
            int c4  = (idx & 15) << 2;
            *(float4*)&Bs[row][c4] =
                *(const float4*)&W[(kt * 32 + row) * N3 + n0 + c4];
        }
        __syncthreads();

        #pragma unroll
        for (int k4 = 0; k4 < 32; k4 += 4) {
            float4 av[4], bv[4];
            #pragma unroll
            for (int r = 0; r < 4; ++r)
                av[r] = *(float4*)&As[ty * 4 + r][k4];
            #pragma unroll
            for (int kk = 0; kk < 4; ++kk)
                bv[kk] = *(float4*)&Bs[k4 + kk][tx * 4];
            #pragma unroll
            for (int r = 0; r < 4; ++r) {
                float a0 = av[r].x, a1 = av[r].y, a2 = av[r].z, a3 = av[r].w;
                acc[r][0] += a0 * bv[0].x + a1 * bv[1].x + a2 * bv[2].x + a3 * bv[3].x;
                acc[r][1] += a0 * bv[0].y + a1 * bv[1].y + a2 * bv[2].y + a3 * bv[3].y;
                acc[r][2] += a0 * bv[0].z + a1 * bv[1].z + a2 * bv[2].z + a3 * bv[3].z;
                acc[r][3] += a0 * bv[0].w + a1 * bv[1].w + a2 * bv[2].w + a3 * bv[3].w;
            }
        }
        __syncthreads();
    }

    // Epilogue: scatter into q/k/v head-major. Tile n-width 64 == HD, so
    // which/h are constant per block, d = tx*4 + c.
    const int which = n0 / Cdim;
    const int h     = (n0 % Cdim) / HDd;
    float* dst = (which == 0) ? g_q : ((which == 1) ? g_k : g_v);
    const int d0 = tx * 4;
    float b0 = bias[n0 + d0 + 0];
    float b1 = bias[n0 + d0 + 1];
    float b2 = bias[n0 + d0 + 2];
    float b3 = bias[n0 + d0 + 3];

    #pragma unroll
    for (int r = 0; r < 4; ++r) {
        int row = m0 + ty * 4 + r;
        int bb  = row / Tdim;
        int t   = row % Tdim;
        float4 o;
        o.x = acc[r][0] + b0;
        o.y = acc[r][1] + b1;
        o.z = acc[r][2] + b2;
        o.w = acc[r][3] + b3;
        *(float4*)&dst[((bb * Hn + h) * Tdim + t) * HDd + d0] = o;
    }
}

// ---------------------------------------------------------------------------
// Kernel 2: causal flash attention, fp32, HD=64.
// Block: 256 threads, BQ=64 queries, BKV=32 keys per iter.
// grid = (T/64, B*H); heavy q-tiles launched first (reversed index).
// ---------------------------------------------------------------------------
__global__ __launch_bounds__(256) void attn_kernel()
{
    __shared__ float Qs[64][64];
    __shared__ float Ks[32][68];   // pad 68 -> conflict-free strided K reads
    __shared__ float Vs[32][64];
    __shared__ float Ps[64][33];

    const int tid = threadIdx.x;
    const int tx = tid & 15;
    const int ty = tid >> 4;
    const int qt = gridDim.x - 1 - blockIdx.x;   // big tiles first
    const int bh = blockIdx.y;

    const float* qptr = g_q + (size_t)bh * Tdim * HDd;
    const float* kptr = g_k + (size_t)bh * Tdim * HDd;
    const float* vptr = g_v + (size_t)bh * Tdim * HDd;

    // Load Q tile, pre-scaled by 1/sqrt(64)
    const float scale = 0.125f;
    #pragma unroll
    for (int it = 0; it < 4; ++it) {
        int idx = tid + it * 256;      // 1024 float4
        int row = idx >> 4;
        int c4  = (idx & 15) << 2;
        float4 qv = *(const float4*)&qptr[(qt * 64 + row) * HDd + c4];
        qv.x *= scale; qv.y *= scale; qv.z *= scale; qv.w *= scale;
        *(float4*)&Qs[row][c4] = qv;
    }

    float m[4], l[4], o[4][4];
    #pragma unroll
    for (int r = 0; r < 4; ++r) {
        m[r] = -1e30f; l[r] = 0.f;
        o[r][0] = o[r][1] = o[r][2] = o[r][3] = 0.f;
    }

    const int ktmax = 2 * qt + 1;
    for (int kt = 0; kt <= ktmax; ++kt) {
        // Load K,V tiles (32x64 each)
        #pragma unroll
        for (int it = 0; it < 2; ++it) {
            int idx = tid + it * 256;
            int row = idx >> 4;
            int c4  = (idx & 15) << 2;
            *(float4*)&Ks[row][c4] =
                *(const float4*)&kptr[(kt * 32 + row) * HDd + c4];
            *(float4*)&Vs[row][c4] =
                *(const float4*)&vptr[(kt * 32 + row) * HDd + c4];
        }
        __syncthreads();

        // S = Q K^T. Thread owns rows i=ty*4+r, cols j = tx + 16*c.
        float s[4][2] = {};
        #pragma unroll
        for (int k4 = 0; k4 < 64; k4 += 4) {
            float4 kv0 = *(float4*)&Ks[tx][k4];
            float4 kv1 = *(float4*)&Ks[tx + 16][k4];
            #pragma unroll
            for (int r = 0; r < 4; ++r) {
                float4 qv = *(float4*)&Qs[ty * 4 + r][k4];
                s[r][0] += qv.x * kv0.x + qv.y * kv0.y + qv.z * kv0.z + qv.w * kv0.w;
                s[r][1] += qv.x * kv1.x + qv.y * kv1.y + qv.z * kv1.z + qv.w * kv1.w;
            }
        }

        // Causal mask (only tiles touching the diagonal need it)
        if (kt * 32 + 31 > qt * 64) {
            #pragma unroll
            for (int r = 0; r < 4; ++r) {
                int ig = qt * 64 + ty * 4 + r;
                #pragma unroll
                for (int c = 0; c < 2; ++c) {
                    int kg = kt * 32 + tx + 16 * c;
                    if (kg > ig) s[r][c] = -1e30f;
                }
            }
        }

        // Online softmax; row spread across 16 lanes (xor 1..8 stays in group)
        #pragma unroll
        for (int r = 0; r < 4; ++r) {
            float mt = fmaxf(s[r][0], s[r][1]);
            #pragma unroll
            for (int off = 8; off >= 1; off >>= 1)
                mt = fmaxf(mt, __shfl_xor_sync(0xffffffffu, mt, off));
            float mnew = fmaxf(m[r], mt);
            float sf   = __expf(m[r] - mnew);
            float p0   = __expf(s[r][0] - mnew);
            float p1   = __expf(s[r][1] - mnew);
            float rs = p0 + p1;
            #pragma unroll
            for (int off = 8; off >= 1; off >>= 1)
                rs += __shfl_xor_sync(0xffffffffu, rs, off);
            l[r] = l[r] * sf + rs;
            m[r] = mnew;
            o[r][0] *= sf; o[r][1] *= sf; o[r][2] *= sf; o[r][3] *= sf;
            Ps[ty * 4 + r][tx]      = p0;
            Ps[ty * 4 + r][tx + 16] = p1;
        }
        __syncthreads();

        // O += P @ V. Thread owns rows i=ty*4+r, dcols = tx*4 + c.
        #pragma unroll 8
        for (int j = 0; j < 32; ++j) {
            float4 vv = *(float4*)&Vs[j][tx * 4];
            #pragma unroll
            for (int r = 0; r < 4; ++r) {
                float pv = Ps[ty * 4 + r][j];
                o[r][0] += pv * vv.x;
                o[r][1] += pv * vv.y;
                o[r][2] += pv * vv.z;
                o[r][3] += pv * vv.w;
            }
        }
        __syncthreads();
    }

    // Normalize and write head-major y
    #pragma unroll
    for (int r = 0; r < 4; ++r) {
        float inv = 1.0f / l[r];
        float4 ov;
        ov.x = o[r][0] * inv; ov.y = o[r][1] * inv;
        ov.z = o[r][2] * inv; ov.w = o[r][3] * inv;
        *(float4*)&g_y[((size_t)bh * Tdim + qt * 64 + ty * 4 + r) * HDd + tx * 4] = ov;
    }
}

// ---------------------------------------------------------------------------
// Kernel 3: proj GEMM  y[4096 x 1024] @ [1024 x 1024] + bias -> out.
// A gathered from head-major g_y. Same tiling as kernel 1.
// ---------------------------------------------------------------------------
__global__ __launch_bounds__(256) void proj_gemm_kernel(
    const float* __restrict__ W, const float* __restrict__ bias,
    float* __restrict__ out)
{
    __shared__ float As[64][32];
    __shared__ float Bs[32][64];

    const int tid = threadIdx.x;
    const int tx = tid & 15;
    const int ty = tid >> 4;
    const int n0 = blockIdx.x * 64;
    const int m0 = blockIdx.y * 64;

    float acc[4][4] = {};

    for (int kt = 0; kt < Cdim / 32; ++kt) {
        const int h  = kt >> 1;              // head for this k-slab
        const int db = (kt & 1) * 32;        // d offset within head
        #pragma unroll
        for (int it = 0; it < 2; ++it) {
            int idx = tid + it * 256;
            int row = idx >> 3;
            int c4  = (idx & 7) << 2;
            int bt  = m0 + row;
            int bb  = bt >> 11;              // /2048
            int t   = bt & 2047;
            *(float4*)&As[row][c4] =
                *(const float4*)&g_y[((bb * Hn + h) * Tdim + t) * HDd + db + c4];
        }
        #pragma unroll
        for (int it = 0; it < 2; ++it) {
            int idx = tid + it * 256;
            int row = idx >> 4;
            int c4  = (idx & 15) << 2;
            *(float4*)&Bs[row][c4] =
                *(const float4*)&W[(kt * 32 + row) * Cdim + n0 + c4];
        }
        __syncthreads();

        #pragma unroll
        for (int k4 = 0; k4 < 32; k4 += 4) {
            float4 av[4], bv[4];
            #pragma unroll
            for (int r = 0; r < 4; ++r)
                av[r] = *(float4*)&As[ty * 4 + r][k4];
            #pragma unroll
            for (int kk = 0; kk < 4; ++kk)
                bv[kk] = *(float4*)&Bs[k4 + kk][tx * 4];
            #pragma unroll
            for (int r = 0; r < 4; ++r) {
                float a0 = av[r].x, a1 = av[r].y, a2 = av[r].z, a3 = av[r].w;
                acc[r][0] += a0 * bv[0].x + a1 * bv[1].x + a2 * bv[2].x + a3 * bv[3].x;
                acc[r][1] += a0 * bv[0].y + a1 * bv[1].y + a2 * bv[2].y + a3 * bv[3].y;
                acc[r][2] += a0 * bv[0].z + a1 * bv[1].z + a2 * bv[2].z + a3 * bv[3].z;
                acc[r][3] += a0 * bv[0].w + a1 * bv[1].w + a2 * bv[2].w + a3 * bv[3].w;
            }
        }
        __syncthreads();
    }

    const int c0 = n0 + tx * 4;
    float b0 = bias[c0 + 0], b1 = bias[c0 + 1], b2 = bias[c0 + 2], b3 = bias[c0 + 3];
    #pragma unroll
    for (int r = 0; r < 4; ++r) {
        int row = m0 + ty * 4 + r;
        float4 ov;
        ov.x = acc[r][0] + b0;
        ov.y = acc[r][1] + b1;
        ov.z = acc[r][2] + b2;
        ov.w = acc[r][3] + b3;
        *(float4*)&out[row * Cdim + c0] = ov;
    }
}

// ---------------------------------------------------------------------------
extern "C" void kernel_launch(void* const* d_in, const int* in_sizes, int n_in,
                              void* d_out, int out_size)
{
    const float* x      = (const float*)d_in[0];
    const float* w_attn = (const float*)d_in[1];
    const float* b_attn = (const float*)d_in[2];
    const float* w_proj = (const float*)d_in[3];
    const float* b_proj = (const float*)d_in[4];
    float* out = (float*)d_out;

    dim3 g1(N3 / 64, Mrows / 64);        // 48 x 64
    qkv_gemm_kernel<<<g1, 256>>>(x, w_attn, b_attn);

    dim3 g2(Tdim / 64, Bdim * Hn);       // 32 x 32
    attn_kernel<<<g2, 256>>>();

    dim3 g3(Cdim / 64, Mrows / 64);      // 16 x 64
    proj_gemm_kernel<<<g3, 256>>>(w_proj, b_proj, out);
}

// round 3
// speedup vs baseline: 1.4870x; 1.4870x over previous
#include <cuda_runtime.h>
#include <cuda_bf16.h>
#include <cstdint>

// Problem constants
#define Bdim 2
#define Tdim 2048
#define Cdim 1024
#define Hn   16
#define HDd  64
#define Mrows (Bdim * Tdim)   // 4096
#define N3    (3 * Cdim)      // 3072

// ---------------------------------------------------------------------------
// Scratch (__device__ globals; allocation-free rule)
// ---------------------------------------------------------------------------
__device__ float g_q[Bdim * Hn * Tdim * HDd];
__device__ float g_k[Bdim * Hn * Tdim * HDd];
__device__ float g_v[Bdim * Hn * Tdim * HDd];

__device__ __nv_bfloat16 g_x_hi[Mrows * Cdim];
__device__ __nv_bfloat16 g_x_lo[Mrows * Cdim];
__device__ __nv_bfloat16 g_wa_hi[N3 * Cdim];     // [N=3072][K=1024]
__device__ __nv_bfloat16 g_wa_lo[N3 * Cdim];
__device__ __nv_bfloat16 g_wp_hi[Cdim * Cdim];   // [N=1024][K=1024]
__device__ __nv_bfloat16 g_wp_lo[Cdim * Cdim];
__device__ __nv_bfloat16 g_y_hi[Mrows * Cdim];   // attn output, [B*T][C]
__device__ __nv_bfloat16 g_y_lo[Mrows * Cdim];

// ---------------------------------------------------------------------------
// PTX helpers (plain sm_103-safe: mma.sync / ldmatrix / cp.async only)
// ---------------------------------------------------------------------------
__device__ __forceinline__ uint32_t smem_u32(const void* p) {
    uint32_t a;
    asm("{ .reg .u64 t; cvta.to.shared.u64 t, %1; cvt.u32.u64 %0, t; }"
        : "=r"(a) : "l"(p));
    return a;
}

#define LDSM4(r, addr) \
    asm volatile("ldmatrix.sync.aligned.m8n8.x4.shared.b16 {%0,%1,%2,%3}, [%4];" \
        : "=r"((r)[0]), "=r"((r)[1]), "=r"((r)[2]), "=r"((r)[3]) : "r"(addr))

#define MMA_BF16(c, a, b0, b1) \
    asm volatile("mma.sync.aligned.m16n8k16.row.col.f32.bf16.bf16.f32 " \
        "{%0,%1,%2,%3}, {%4,%5,%6,%7}, {%8,%9}, {%0,%1,%2,%3};" \
        : "+f"((c)[0]), "+f"((c)[1]), "+f"((c)[2]), "+f"((c)[3]) \
        : "r"((a)[0]), "r"((a)[1]), "r"((a)[2]), "r"((a)[3]), "r"(b0), "r"(b1))

#define CP_ASYNC16(dst, src) \
    asm volatile("cp.async.cg.shared.global [%0], [%1], 16;" :: "r"(dst), "l"(src))
#define CP_COMMIT() asm volatile("cp.async.commit_group;")

__device__ __forceinline__ void split_bf16(float v, __nv_bfloat16& h, __nv_bfloat16& l) {
    h = __float2bfloat16(v);
    l = __float2bfloat16(v - __bfloat162float(h));
}

// ---------------------------------------------------------------------------
// Prep kernels
// ---------------------------------------------------------------------------
__global__ __launch_bounds__(256) void prep_x_kernel(const float* __restrict__ x) {
    int i = (blockIdx.x * 256 + threadIdx.x) * 4;
    float4 v = *(const float4*)&x[i];
    __nv_bfloat16 h0, l0, h1, l1, h2, l2, h3, l3;
    split_bf16(v.x, h0, l0); split_bf16(v.y, h1, l1);
    split_bf16(v.z, h2, l2); split_bf16(v.w, h3, l3);
    *(__nv_bfloat162*)&g_x_hi[i]     = __nv_bfloat162(h0, h1);
    *(__nv_bfloat162*)&g_x_hi[i + 2] = __nv_bfloat162(h2, h3);
    *(__nv_bfloat162*)&g_x_lo[i]     = __nv_bfloat162(l0, l1);
    *(__nv_bfloat162*)&g_x_lo[i + 2] = __nv_bfloat162(l2, l3);
}

// Transpose W [K, N] -> Wt_hi/Wt_lo [N, K] (bf16 split)
__global__ __launch_bounds__(256) void prep_w_kernel(
    const float* __restrict__ W, __nv_bfloat16* __restrict__ Wt_hi,
    __nv_bfloat16* __restrict__ Wt_lo, int K, int N) {
    __shared__ float tile[32][33];
    int n0 = blockIdx.x * 32, k0 = blockIdx.y * 32;
    int tx = threadIdx.x & 31, ty = threadIdx.x >> 5;   // 32 x 8
    #pragma unroll
    for (int r = 0; r < 32; r += 8)
        tile[ty + r][tx] = W[(size_t)(k0 + ty + r) * N + n0 + tx];
    __syncthreads();
    #pragma unroll
    for (int r = 0; r < 32; r += 8) {
        float v = tile[tx][ty + r];                 // = W[k0+tx][n0+ty+r]
        __nv_bfloat16 h, l; split_bf16(v, h, l);
        size_t o = (size_t)(n0 + ty + r) * K + k0 + tx;
        Wt_hi[o] = h; Wt_lo[o] = l;
    }
}

// ---------------------------------------------------------------------------
// mma.sync bf16x3 GEMM: D[128x128] = A[Mx1024] * B[Nx1024]^T + bias
// 256 threads, 8 warps (4x2), warp tile 32x64, BK=32, 2-stage cp.async.
// mode 0: scatter to g_q/g_k/g_v head-major.  mode 1: write out row-major.
// Smem per array per stage: 128 rows x 40 bf16 (padded) = 10240 B.
// ---------------------------------------------------------------------------
#define GSTAGE 10240
#define GARR   20480
#define GSMEM  (4 * GARR)   // 81920

__global__ __launch_bounds__(256, 2)
void gemm_bf16x3_kernel(const __nv_bfloat16* __restrict__ Ah,
                        const __nv_bfloat16* __restrict__ Al,
                        const __nv_bfloat16* __restrict__ Bh,
                        const __nv_bfloat16* __restrict__ Bl,
                        const float* __restrict__ bias,
                        float* __restrict__ out, int mode) {
    extern __shared__ __align__(16) char dynsm[];

    const int tid  = threadIdx.x;
    const int lane = tid & 31;
    const int wid  = tid >> 5;
    const int wm   = wid & 3;        // warp row: 32 rows each
    const int wn   = wid >> 2;       // warp col: 64 cols each
    const int n0 = blockIdx.x * 128;
    const int m0 = blockIdx.y * 128;

    const uint32_t uAh = smem_u32(dynsm);
    const uint32_t uAl = uAh + GARR;
    const uint32_t uBh = uAh + 2 * GARR;
    const uint32_t uBl = uAh + 3 * GARR;

    // ldmatrix per-thread offset: row (lane&15), col-half (lane>>4)*8 bf16
    const uint32_t lm_off = (uint32_t)((lane & 15) * 80 + (lane >> 4) * 16);

    float acc[2][8][4] = {};

    auto issue = [&](int ch) {
        const uint32_t soff = (uint32_t)(ch & 1) * GSTAGE;
        const int k0 = ch * 32;
        #pragma unroll
        for (int it = 0; it < 2; ++it) {
            int idx = tid + it * 256;          // 512 chunks/array
            int row = idx >> 2;
            int c   = idx & 3;
            uint32_t so = soff + row * 80 + c * 16;
            size_t ga = (size_t)(m0 + row) * Cdim + k0 + c * 8;
            size_t gb = (size_t)(n0 + row) * Cdim + k0 + c * 8;
            CP_ASYNC16(uAh + so, Ah + ga);
            CP_ASYNC16(uAl + so, Al + ga);
            CP_ASYNC16(uBh + so, Bh + gb);
            CP_ASYNC16(uBl + so, Bl + gb);
        }
        CP_COMMIT();
    };

    const int NCH = Cdim / 32;   // 32
    issue(0);
    issue(1);

    for (int ch = 0; ch < NCH; ++ch) {
        if (ch + 1 < NCH) { asm volatile("cp.async.wait_group 1;"); }
        else              { asm volatile("cp.async.wait_group 0;"); }
        __syncthreads();

        const uint32_t soff = (uint32_t)(ch & 1) * GSTAGE;
        #pragma unroll
        for (int k16 = 0; k16 < 2; ++k16) {
            const uint32_t akoff = soff + k16 * 32 + lm_off;
            uint32_t ah[8], al[8];
            #pragma unroll
            for (int mt = 0; mt < 2; ++mt) {
                uint32_t rowb = (uint32_t)((wm * 32 + mt * 16) * 80);
                LDSM4(ah + mt * 4, uAh + akoff + rowb);
                LDSM4(al + mt * 4, uAl + akoff + rowb);
            }
            #pragma unroll
            for (int np = 0; np < 4; ++np) {
                uint32_t rowb = (uint32_t)((wn * 64 + np * 16) * 80);
                uint32_t bh[4], bl[4];
                LDSM4(bh, uBh + akoff + rowb);
                LDSM4(bl, uBl + akoff + rowb);
                #pragma unroll
                for (int mt = 0; mt < 2; ++mt) {
                    #pragma unroll
                    for (int hf = 0; hf < 2; ++hf) {
                        float* c = acc[mt][np * 2 + hf];
                        MMA_BF16(c, ah + mt * 4, bh[hf], bh[2 + hf]);  // hi*hi
                        MMA_BF16(c, ah + mt * 4, bl[hf], bl[2 + hf]);  // hi*lo
                        MMA_BF16(c, al + mt * 4, bh[hf], bh[2 + hf]);  // lo*hi
                    }
                }
            }
        }
        __syncthreads();
        if (ch + 2 < NCH) issue(ch + 2);
    }

    // Epilogue
    const int which = n0 >> 10;
    float* qkv = (which == 0) ? g_q : ((which == 1) ? g_k : g_v);

    #pragma unroll
    for (int mt = 0; mt < 2; ++mt) {
        const int rg0 = m0 + wm * 32 + mt * 16 + (lane >> 2);
        const int bb  = rg0 >> 11;
        const int t0  = rg0 & 2047;
        #pragma unroll
        for (int nt = 0; nt < 8; ++nt) {
            const int ncol = n0 + wn * 64 + nt * 8 + (lane & 3) * 2;
            const float2 bv = *(const float2*)&bias[ncol];
            float2 v0, v1;
            v0.x = acc[mt][nt][0] + bv.x;
            v0.y = acc[mt][nt][1] + bv.y;
            v1.x = acc[mt][nt][2] + bv.x;
            v1.y = acc[mt][nt][3] + bv.y;
            if (mode == 0) {
                const int nc = ncol & 1023;
                const int h  = nc >> 6;
                const int d  = nc & 63;
                size_t base = (((size_t)bb * Hn + h) * Tdim + t0) * HDd + d;
                *(float2*)&qkv[base]            = v0;
                *(float2*)&qkv[base + 8 * HDd]  = v1;   // row +8
            } else {
                size_t base = (size_t)rg0 * Cdim + ncol;
                *(float2*)&out[base]            = v0;
                *(float2*)&out[base + 8 * Cdim] = v1;
            }
        }
    }
}

// ---------------------------------------------------------------------------
// Causal flash attention, fp32, HD=64 (unchanged from R1-passing version;
// output pre-split to bf16 hi/lo in [B*T, C] layout).
// ---------------------------------------------------------------------------
__global__ __launch_bounds__(256) void attn_kernel() {
    __shared__ float Qs[64][64];
    __shared__ float Ks[32][68];
    __shared__ float Vs[32][64];
    __shared__ float Ps[64][33];

    const int tid = threadIdx.x;
    const int tx = tid & 15;
    const int ty = tid >> 4;
    const int qt = gridDim.x - 1 - blockIdx.x;
    const int bh = blockIdx.y;

    const float* qptr = g_q + (size_t)bh * Tdim * HDd;
    const float* kptr = g_k + (size_t)bh * Tdim * HDd;
    const float* vptr = g_v + (size_t)bh * Tdim * HDd;

    const float scale = 0.125f;
    #pragma unroll
    for (int it = 0; it < 4; ++it) {
        int idx = tid + it * 256;
        int row = idx >> 4;
        int c4  = (idx & 15) << 2;
        float4 qv = *(const float4*)&qptr[(qt * 64 + row) * HDd + c4];
        qv.x *= scale; qv.y *= scale; qv.z *= scale; qv.w *= scale;
        *(float4*)&Qs[row][c4] = qv;
    }

    float m[4], l[4], o[4][4];
    #pragma unroll
    for (int r = 0; r < 4; ++r) {
        m[r] = -1e30f; l[r] = 0.f;
        o[r][0] = o[r][1] = o[r][2] = o[r][3] = 0.f;
    }

    const int ktmax = 2 * qt + 1;
    for (int kt = 0; kt <= ktmax; ++kt) {
        #pragma unroll
        for (int it = 0; it < 2; ++it) {
            int idx = tid + it * 256;
            int row = idx >> 4;
            int c4  = (idx & 15) << 2;
            *(float4*)&Ks[row][c4] = *(const float4*)&kptr[(kt * 32 + row) * HDd + c4];
            *(float4*)&Vs[row][c4] = *(const float4*)&vptr[(kt * 32 + row) * HDd + c4];
        }
        __syncthreads();

        float s[4][2] = {};
        #pragma unroll
        for (int k4 = 0; k4 < 64; k4 += 4) {
            float4 kv0 = *(float4*)&Ks[tx][k4];
            float4 kv1 = *(float4*)&Ks[tx + 16][k4];
            #pragma unroll
            for (int r = 0; r < 4; ++r) {
                float4 qv = *(float4*)&Qs[ty * 4 + r][k4];
                s[r][0] += qv.x * kv0.x + qv.y * kv0.y + qv.z * kv0.z + qv.w * kv0.w;
                s[r][1] += qv.x * kv1.x + qv.y * kv1.y + qv.z * kv1.z + qv.w * kv1.w;
            }
        }

        if (kt * 32 + 31 > qt * 64) {
            #pragma unroll
            for (int r = 0; r < 4; ++r) {
                int ig = qt * 64 + ty * 4 + r;
                #pragma unroll
                for (int c = 0; c < 2; ++c) {
                    int kg = kt * 32 + tx + 16 * c;
                    if (kg > ig) s[r][c] = -1e30f;
                }
            }
        }

        #pragma unroll
        for (int r = 0; r < 4; ++r) {
            float mt = fmaxf(s[r][0], s[r][1]);
            #pragma unroll
            for (int off = 8; off >= 1; off >>= 1)
                mt = fmaxf(mt, __shfl_xor_sync(0xffffffffu, mt, off));
            float mnew = fmaxf(m[r], mt);
            float sf = __expf(m[r] - mnew);
            float p0 = __expf(s[r][0] - mnew);
            float p1 = __expf(s[r][1] - mnew);
            float rs = p0 + p1;
            #pragma unroll
            for (int off = 8; off >= 1; off >>= 1)
                rs += __shfl_xor_sync(0xffffffffu, rs, off);
            l[r] = l[r] * sf + rs;
            m[r] = mnew;
            o[r][0] *= sf; o[r][1] *= sf; o[r][2] *= sf; o[r][3] *= sf;
            Ps[ty * 4 + r][tx]      = p0;
            Ps[ty * 4 + r][tx + 16] = p1;
        }
        __syncthreads();

        #pragma unroll 8
        for (int j = 0; j < 32; ++j) {
            float4 vv = *(float4*)&Vs[j][tx * 4];
            #pragma unroll
            for (int r = 0; r < 4; ++r) {
                float pv = Ps[ty * 4 + r][j];
                o[r][0] += pv * vv.x;
                o[r][1] += pv * vv.y;
                o[r][2] += pv * vv.z;
                o[r][3] += pv * vv.w;
            }
        }
        __syncthreads();
    }

    const int b = bh >> 4;
    const int h = bh & 15;
    #pragma unroll
    for (int r = 0; r < 4; ++r) {
        float inv = 1.0f / l[r];
        int rg = b * Tdim + qt * 64 + ty * 4 + r;
        size_t base = (size_t)rg * Cdim + h * HDd + tx * 4;
        __nv_bfloat16 h0, l0, h1, l1, h2, l2, h3, l3;
        split_bf16(o[r][0] * inv, h0, l0);
        split_bf16(o[r][1] * inv, h1, l1);
        split_bf16(o[r][2] * inv, h2, l2);
        split_bf16(o[r][3] * inv, h3, l3);
        *(__nv_bfloat162*)&g_y_hi[base]     = __nv_bfloat162(h0, h1);
        *(__nv_bfloat162*)&g_y_hi[base + 2] = __nv_bfloat162(h2, h3);
        *(__nv_bfloat162*)&g_y_lo[base]     = __nv_bfloat162(l0, l1);
        *(__nv_bfloat162*)&g_y_lo[base + 2] = __nv_bfloat162(l2, l3);
    }
}

// ---------------------------------------------------------------------------
extern "C" void kernel_launch(void* const* d_in, const int* in_sizes, int n_in,
                              void* d_out, int out_size) {
    const float* x      = (const float*)d_in[0];
    const float* w_attn = (const float*)d_in[1];
    const float* b_attn = (const float*)d_in[2];
    const float* w_proj = (const float*)d_in[3];
    const float* b_proj = (const float*)d_in[4];
    float* out = (float*)d_out;

    static bool attr_set = false;
    if (!attr_set) {
        cudaFuncSetAttribute(gemm_bf16x3_kernel,
                             cudaFuncAttributeMaxDynamicSharedMemorySize, GSMEM);
        attr_set = true;
    }

    __nv_bfloat16 *x_hi, *x_lo, *wa_hi, *wa_lo, *wp_hi, *wp_lo, *y_hi, *y_lo;
    cudaGetSymbolAddress((void**)&x_hi, g_x_hi);
    cudaGetSymbolAddress((void**)&x_lo, g_x_lo);
    cudaGetSymbolAddress((void**)&wa_hi, g_wa_hi);
    cudaGetSymbolAddress((void**)&wa_lo, g_wa_lo);
    cudaGetSymbolAddress((void**)&wp_hi, g_wp_hi);
    cudaGetSymbolAddress((void**)&wp_lo, g_wp_lo);
    cudaGetSymbolAddress((void**)&y_hi, g_y_hi);
    cudaGetSymbolAddress((void**)&y_lo, g_y_lo);

    // Prep: split x, transpose+split weights
    prep_x_kernel<<<Mrows * Cdim / (256 * 4), 256>>>(x);
    {
        dim3 ga(N3 / 32, Cdim / 32);
        prep_w_kernel<<<ga, 256>>>(w_attn, wa_hi, wa_lo, Cdim, N3);
        dim3 gp(Cdim / 32, Cdim / 32);
        prep_w_kernel<<<gp, 256>>>(w_proj, wp_hi, wp_lo, Cdim, Cdim);
    }

    // QKV GEMM: [4096 x 1024] x [3072 x 1024]^T
    dim3 g1(N3 / 128, Mrows / 128);     // 24 x 32
    gemm_bf16x3_kernel<<<g1, 256, GSMEM>>>(x_hi, x_lo, wa_hi, wa_lo,
                                           b_attn, nullptr, 0);

    // Attention
    dim3 g2(Tdim / 64, Bdim * Hn);
    attn_kernel<<<g2, 256>>>();

    // Proj GEMM: [4096 x 1024] x [1024 x 1024]^T
    dim3 g3(Cdim / 128, Mrows / 128);   // 8 x 32
    gemm_bf16x3_kernel<<<g3, 256, GSMEM>>>(y_hi, y_lo, wp_hi, wp_lo,
                                           b_proj, out, 1);
}

// round 4
// speedup vs baseline: 2.6105x; 1.7555x over previous
#include <cuda_runtime.h>
#include <cuda_bf16.h>
#include <cstdint>

// Problem constants
#define Bdim 2
#define Tdim 2048
#define Cdim 1024
#define Hn   16
#define HDd  64
#define Mrows (Bdim * Tdim)   // 4096
#define N3    (3 * Cdim)      // 3072

// ---------------------------------------------------------------------------
// Scratch (__device__ globals; allocation-free rule)
// ---------------------------------------------------------------------------
__device__ __nv_bfloat16 g_x_hi[Mrows * Cdim];
__device__ __nv_bfloat16 g_x_lo[Mrows * Cdim];
__device__ __nv_bfloat16 g_wa_hi[N3 * Cdim];     // [N=3072][K=1024]
__device__ __nv_bfloat16 g_wa_lo[N3 * Cdim];
__device__ __nv_bfloat16 g_wp_hi[Cdim * Cdim];   // [N=1024][K=1024]
__device__ __nv_bfloat16 g_wp_lo[Cdim * Cdim];
__device__ __nv_bfloat16 g_y_hi[Mrows * Cdim];   // attn output, [B*T][C]
__device__ __nv_bfloat16 g_y_lo[Mrows * Cdim];

// Split q/k/v, head-major [B*H][T][HD]; q pre-scaled by 1/sqrt(HD)
__device__ __nv_bfloat16 g_qh[Bdim * Hn * Tdim * HDd];
__device__ __nv_bfloat16 g_ql[Bdim * Hn * Tdim * HDd];
__device__ __nv_bfloat16 g_kh[Bdim * Hn * Tdim * HDd];
__device__ __nv_bfloat16 g_kl[Bdim * Hn * Tdim * HDd];
__device__ __nv_bfloat16 g_vh[Bdim * Hn * Tdim * HDd];
__device__ __nv_bfloat16 g_vl[Bdim * Hn * Tdim * HDd];

// ---------------------------------------------------------------------------
// PTX helpers (plain sm_103-safe: mma.sync / ldmatrix / cp.async only)
// ---------------------------------------------------------------------------
__device__ __forceinline__ uint32_t smem_u32(const void* p) {
    uint32_t a;
    asm("{ .reg .u64 t; cvta.to.shared.u64 t, %1; cvt.u32.u64 %0, t; }"
        : "=r"(a) : "l"(p));
    return a;
}

#define LDSM4(r, addr) \
    asm volatile("ldmatrix.sync.aligned.m8n8.x4.shared.b16 {%0,%1,%2,%3}, [%4];" \
        : "=r"((r)[0]), "=r"((r)[1]), "=r"((r)[2]), "=r"((r)[3]) : "r"(addr))

#define LDSM4T(r, addr) \
    asm volatile("ldmatrix.sync.aligned.m8n8.x4.trans.shared.b16 {%0,%1,%2,%3}, [%4];" \
        : "=r"((r)[0]), "=r"((r)[1]), "=r"((r)[2]), "=r"((r)[3]) : "r"(addr))

#define MMA_BF16(c, a, b0, b1) \
    asm volatile("mma.sync.aligned.m16n8k16.row.col.f32.bf16.bf16.f32 " \
        "{%0,%1,%2,%3}, {%4,%5,%6,%7}, {%8,%9}, {%0,%1,%2,%3};" \
        : "+f"((c)[0]), "+f"((c)[1]), "+f"((c)[2]), "+f"((c)[3]) \
        : "r"((a)[0]), "r"((a)[1]), "r"((a)[2]), "r"((a)[3]), "r"(b0), "r"(b1))

#define CP_ASYNC16(dst, src) \
    asm volatile("cp.async.cg.shared.global [%0], [%1], 16;" :: "r"(dst), "l"(src))
#define CP_COMMIT() asm volatile("cp.async.commit_group;")

__device__ __forceinline__ void split_bf16(float v, __nv_bfloat16& h, __nv_bfloat16& l) {
    h = __float2bfloat16(v);
    l = __float2bfloat16(v - __bfloat162float(h));
}

__device__ __forceinline__ void pack_split2(float v0, float v1,
                                            uint32_t& hi, uint32_t& lo) {
    __nv_bfloat16 h0, l0, h1, l1;
    split_bf16(v0, h0, l0);
    split_bf16(v1, h1, l1);
    __nv_bfloat162 hh(h0, h1), ll(l0, l1);
    hi = *(uint32_t*)&hh;
    lo = *(uint32_t*)&ll;
}

// ---------------------------------------------------------------------------
// Prep kernels
// ---------------------------------------------------------------------------
__global__ __launch_bounds__(256) void prep_x_kernel(const float* __restrict__ x) {
    int i = (blockIdx.x * 256 + threadIdx.x) * 4;
    float4 v = *(const float4*)&x[i];
    uint32_t h0, l0, h1, l1;
    pack_split2(v.x, v.y, h0, l0);
    pack_split2(v.z, v.w, h1, l1);
    *(uint32_t*)&g_x_hi[i]     = h0;
    *(uint32_t*)&g_x_hi[i + 2] = h1;
    *(uint32_t*)&g_x_lo[i]     = l0;
    *(uint32_t*)&g_x_lo[i + 2] = l1;
}

// Transpose W [K, N] -> Wt_hi/Wt_lo [N, K] (bf16 split)
__global__ __launch_bounds__(256) void prep_w_kernel(
    const float* __restrict__ W, __nv_bfloat16* __restrict__ Wt_hi,
    __nv_bfloat16* __restrict__ Wt_lo, int K, int N) {
    __shared__ float tile[32][33];
    int n0 = blockIdx.x * 32, k0 = blockIdx.y * 32;
    int tx = threadIdx.x & 31, ty = threadIdx.x >> 5;   // 32 x 8
    #pragma unroll
    for (int r = 0; r < 32; r += 8)
        tile[ty + r][tx] = W[(size_t)(k0 + ty + r) * N + n0 + tx];
    __syncthreads();
    #pragma unroll
    for (int r = 0; r < 32; r += 8) {
        float v = tile[tx][ty + r];
        __nv_bfloat16 h, l; split_bf16(v, h, l);
        size_t o = (size_t)(n0 + ty + r) * K + k0 + tx;
        Wt_hi[o] = h; Wt_lo[o] = l;
    }
}

// ---------------------------------------------------------------------------
// mma.sync bf16x3 GEMM: D[128x128] = A[Mx1024] * B[Nx1024]^T + bias
// mode 0: write split bf16 q (x0.125) / k / v head-major.
// mode 1: write fp32 out row-major.
// ---------------------------------------------------------------------------
#define GSTAGE 10240
#define GARR   20480
#define GSMEM  (4 * GARR)   // 81920

__global__ __launch_bounds__(256, 2)
void gemm_bf16x3_kernel(const __nv_bfloat16* __restrict__ Ah,
                        const __nv_bfloat16* __restrict__ Al,
                        const __nv_bfloat16* __restrict__ Bh,
                        const __nv_bfloat16* __restrict__ Bl,
                        const float* __restrict__ bias,
                        float* __restrict__ out, int mode) {
    extern __shared__ __align__(16) char dynsm[];

    const int tid  = threadIdx.x;
    const int lane = tid & 31;
    const int wid  = tid >> 5;
    const int wm   = wid & 3;        // warp row: 32 rows each
    const int wn   = wid >> 2;       // warp col: 64 cols each
    const int n0 = blockIdx.x * 128;
    const int m0 = blockIdx.y * 128;

    const uint32_t uAh = smem_u32(dynsm);
    const uint32_t uAl = uAh + GARR;
    const uint32_t uBh = uAh + 2 * GARR;
    const uint32_t uBl = uAh + 3 * GARR;

    const uint32_t lm_off = (uint32_t)((lane & 15) * 80 + (lane >> 4) * 16);

    float acc[2][8][4] = {};

    auto issue = [&](int ch) {
        const uint32_t soff = (uint32_t)(ch & 1) * GSTAGE;
        const int k0 = ch * 32;
        #pragma unroll
        for (int it = 0; it < 2; ++it) {
            int idx = tid + it * 256;
            int row = idx >> 2;
            int c   = idx & 3;
            uint32_t so = soff + row * 80 + c * 16;
            size_t ga = (size_t)(m0 + row) * Cdim + k0 + c * 8;
            size_t gb = (size_t)(n0 + row) * Cdim + k0 + c * 8;
            CP_ASYNC16(uAh + so, Ah + ga);
            CP_ASYNC16(uAl + so, Al + ga);
            CP_ASYNC16(uBh + so, Bh + gb);
            CP_ASYNC16(uBl + so, Bl + gb);
        }
        CP_COMMIT();
    };

    const int NCH = Cdim / 32;   // 32
    issue(0);
    issue(1);

    for (int ch = 0; ch < NCH; ++ch) {
        if (ch + 1 < NCH) { asm volatile("cp.async.wait_group 1;"); }
        else              { asm volatile("cp.async.wait_group 0;"); }
        __syncthreads();

        const uint32_t soff = (uint32_t)(ch & 1) * GSTAGE;
        #pragma unroll
        for (int k16 = 0; k16 < 2; ++k16) {
            const uint32_t akoff = soff + k16 * 32 + lm_off;
            uint32_t ah[8], al[8];
            #pragma unroll
            for (int mt = 0; mt < 2; ++mt) {
                uint32_t rowb = (uint32_t)((wm * 32 + mt * 16) * 80);
                LDSM4(ah + mt * 4, uAh + akoff + rowb);
                LDSM4(al + mt * 4, uAl + akoff + rowb);
            }
            #pragma unroll
            for (int np = 0; np < 4; ++np) {
                uint32_t rowb = (uint32_t)((wn * 64 + np * 16) * 80);
                uint32_t bh[4], bl[4];
                LDSM4(bh, uBh + akoff + rowb);
                LDSM4(bl, uBl + akoff + rowb);
                #pragma unroll
                for (int mt = 0; mt < 2; ++mt) {
                    #pragma unroll
                    for (int hf = 0; hf < 2; ++hf) {
                        float* c = acc[mt][np * 2 + hf];
                        MMA_BF16(c, ah + mt * 4, bh[hf], bh[2 + hf]);
                        MMA_BF16(c, ah + mt * 4, bl[hf], bl[2 + hf]);
                        MMA_BF16(c, al + mt * 4, bh[hf], bh[2 + hf]);
                    }
                }
            }
        }
        __syncthreads();
        if (ch + 2 < NCH) issue(ch + 2);
    }

    // Epilogue
    if (mode == 0) {
        // Warp covers 64 cols = exactly one head of one of q/k/v.
        const int ncol0 = n0 + wn * 64;
        const int which = ncol0 >> 10;
        const int hh    = (ncol0 & 1023) >> 6;
        __nv_bfloat16* dh = (which == 0) ? g_qh : ((which == 1) ? g_kh : g_vh);
        __nv_bfloat16* dl = (which == 0) ? g_ql : ((which == 1) ? g_kl : g_vl);
        const float qs = (which == 0) ? 0.125f : 1.0f;
        #pragma unroll
        for (int mt = 0; mt < 2; ++mt) {
            const int rg0 = m0 + wm * 32 + mt * 16 + (lane >> 2);
            const int bb  = rg0 >> 11;
            const int t0  = rg0 & 2047;
            const size_t rbase = (((size_t)bb * Hn + hh) * Tdim + t0) * HDd;
            #pragma unroll
            for (int nt = 0; nt < 8; ++nt) {
                const int d = nt * 8 + (lane & 3) * 2;
                const float2 bv = *(const float2*)&bias[ncol0 + d];
                uint32_t hi, lo;
                pack_split2((acc[mt][nt][0] + bv.x) * qs,
                            (acc[mt][nt][1] + bv.y) * qs, hi, lo);
                *(uint32_t*)&dh[rbase + d] = hi;
                *(uint32_t*)&dl[rbase + d] = lo;
                pack_split2((acc[mt][nt][2] + bv.x) * qs,
                            (acc[mt][nt][3] + bv.y) * qs, hi, lo);
                *(uint32_t*)&dh[rbase + 8 * HDd + d] = hi;
                *(uint32_t*)&dl[rbase + 8 * HDd + d] = lo;
            }
        }
    } else {
        #pragma unroll
        for (int mt = 0; mt < 2; ++mt) {
            const int rg0 = m0 + wm * 32 + mt * 16 + (lane >> 2);
            #pragma unroll
            for (int nt = 0; nt < 8; ++nt) {
                const int ncol = n0 + wn * 64 + nt * 8 + (lane & 3) * 2;
                const float2 bv = *(const float2*)&bias[ncol];
                float2 v0, v1;
                v0.x = acc[mt][nt][0] + bv.x;
                v0.y = acc[mt][nt][1] + bv.y;
                v1.x = acc[mt][nt][2] + bv.x;
                v1.y = acc[mt][nt][3] + bv.y;
                size_t base = (size_t)rg0 * Cdim + ncol;
                *(float2*)&out[base]            = v0;
                *(float2*)&out[base + 8 * Cdim] = v1;
            }
        }
    }
}

// ---------------------------------------------------------------------------
// mma.sync causal flash attention, bf16x3 split for QK^T and PV.
// BQ=128 (8 warps x 16 rows), BKV=64, HD=64. smem row stride 72 bf16 (144B).
// ---------------------------------------------------------------------------
#define ARS 144                      // row stride bytes
#define AQH 0
#define AQL 18432
#define AKH 36864
#define AKL 46080
#define AVH 55296
#define AVL 64512
#define ASMEM 73728

__global__ __launch_bounds__(256, 2) void attn_mma_kernel() {
    extern __shared__ __align__(16) char asmem[];
    const int tid = threadIdx.x;
    const int lane = tid & 31;
    const int w = tid >> 5;
    const int qt = gridDim.x - 1 - blockIdx.x;   // heavy tiles first
    const int bh = blockIdx.y;

    const uint32_t uS = smem_u32(asmem);
    const size_t hbase = (size_t)bh * Tdim * HDd;
    const __nv_bfloat16* qh = g_qh + hbase;
    const __nv_bfloat16* ql = g_ql + hbase;
    const __nv_bfloat16* kh = g_kh + hbase;
    const __nv_bfloat16* kl = g_kl + hbase;
    const __nv_bfloat16* vh = g_vh + hbase;
    const __nv_bfloat16* vl = g_vl + hbase;

    // Q tile load: 128 rows x 64 (hi+lo)
    #pragma unroll
    for (int it = 0; it < 4; ++it) {
        int idx = tid + it * 256;
        int row = idx >> 3, c = idx & 7;
        uint32_t dst = row * ARS + c * 16;
        size_t src = (size_t)(qt * 128 + row) * HDd + c * 8;
        CP_ASYNC16(uS + AQH + dst, qh + src);
        CP_ASYNC16(uS + AQL + dst, ql + src);
    }
    CP_COMMIT();

    const int r4 = lane >> 2;
    const int c2 = (lane & 3) * 2;
    float m0 = -1e30f, m1 = -1e30f, l0 = 0.f, l1 = 0.f;
    float O[8][4] = {};

    const int nkt = 2 * qt + 2;
    for (int kt = 0; kt < nkt; ++kt) {
        __syncthreads();   // previous compute done with K/V smem
        #pragma unroll
        for (int it = 0; it < 2; ++it) {
            int idx = tid + it * 256;
            int row = idx >> 3, c = idx & 7;
            uint32_t dst = row * ARS + c * 16;
            size_t src = (size_t)(kt * 64 + row) * HDd + c * 8;
            CP_ASYNC16(uS + AKH + dst, kh + src);
            CP_ASYNC16(uS + AKL + dst, kl + src);
            CP_ASYNC16(uS + AVH + dst, vh + src);
            CP_ASYNC16(uS + AVL + dst, vl + src);
        }
        CP_COMMIT();
        asm volatile("cp.async.wait_group 0;");
        __syncthreads();

        // ---- S = Q K^T (3-term split), per warp 16 x 64 ----
        float S[8][4] = {};
        #pragma unroll
        for (int k16 = 0; k16 < 4; ++k16) {
            const uint32_t qoff =
                (uint32_t)((w * 16 + (lane & 15)) * ARS + (lane >> 4) * 16 + k16 * 32);
            uint32_t aqh[4], aql[4];
            LDSM4(aqh, uS + AQH + qoff);
            LDSM4(aql, uS + AQL + qoff);
            #pragma unroll
            for (int kp = 0; kp < 4; ++kp) {
                const uint32_t koff =
                    (uint32_t)((kp * 16 + (lane & 15)) * ARS + (lane >> 4) * 16 + k16 * 32);
                uint32_t bkh[4], bkl[4];
                LDSM4(bkh, uS + AKH + koff);
                LDSM4(bkl, uS + AKL + koff);
                #pragma unroll
                for (int hf = 0; hf < 2; ++hf) {
                    float* c = S[kp * 2 + hf];
                    MMA_BF16(c, aqh, bkh[hf], bkh[2 + hf]);
                    MMA_BF16(c, aqh, bkl[hf], bkl[2 + hf]);
                    MMA_BF16(c, aql, bkh[hf], bkh[2 + hf]);
                }
            }
        }

        // ---- causal mask (diagonal-crossing tiles only) ----
        const int row0 = qt * 128 + w * 16 + r4;
        if (kt * 64 + 63 > qt * 128 + w * 16) {
            #pragma unroll
            for (int j = 0; j < 8; ++j) {
                const int cb = kt * 64 + j * 8 + c2;
                if (cb     > row0)     S[j][0] = -1e30f;
                if (cb + 1 > row0)     S[j][1] = -1e30f;
                if (cb     > row0 + 8) S[j][2] = -1e30f;
                if (cb + 1 > row0 + 8) S[j][3] = -1e30f;
            }
        }

        // ---- online softmax on fragments ----
        float mt0 = -1e30f, mt1 = -1e30f;
        #pragma unroll
        for (int j = 0; j < 8; ++j) {
            mt0 = fmaxf(mt0, fmaxf(S[j][0], S[j][1]));
            mt1 = fmaxf(mt1, fmaxf(S[j][2], S[j][3]));
        }
        mt0 = fmaxf(mt0, __shfl_xor_sync(0xffffffffu, mt0, 1));
        mt0 = fmaxf(mt0, __shfl_xor_sync(0xffffffffu, mt0, 2));
        mt1 = fmaxf(mt1, __shfl_xor_sync(0xffffffffu, mt1, 1));
        mt1 = fmaxf(mt1, __shfl_xor_sync(0xffffffffu, mt1, 2));
        const float mn0 = fmaxf(m0, mt0);
        const float mn1 = fmaxf(m1, mt1);
        const float sf0 = __expf(m0 - mn0);
        const float sf1 = __expf(m1 - mn1);
        m0 = mn0; m1 = mn1;

        float rs0 = 0.f, rs1 = 0.f;
        #pragma unroll
        for (int j = 0; j < 8; ++j) {
            S[j][0] = __expf(S[j][0] - m0);
            S[j][1] = __expf(S[j][1] - m0);
            S[j][2] = __expf(S[j][2] - m1);
            S[j][3] = __expf(S[j][3] - m1);
            rs0 += S[j][0] + S[j][1];
            rs1 += S[j][2] + S[j][3];
        }
        rs0 += __shfl_xor_sync(0xffffffffu, rs0, 1);
        rs0 += __shfl_xor_sync(0xffffffffu, rs0, 2);
        rs1 += __shfl_xor_sync(0xffffffffu, rs1, 1);
        rs1 += __shfl_xor_sync(0xffffffffu, rs1, 2);
        l0 = l0 * sf0 + rs0;
        l1 = l1 * sf1 + rs1;
        #pragma unroll
        for (int j = 0; j < 8; ++j) {
            O[j][0] *= sf0; O[j][1] *= sf0;
            O[j][2] *= sf1; O[j][3] *= sf1;
        }

        // ---- O += P V (3-term split); V B-frags via ldmatrix.trans ----
        #pragma unroll
        for (int s = 0; s < 4; ++s) {
            uint32_t ph[4], pl[4];
            pack_split2(S[2 * s][0],     S[2 * s][1],     ph[0], pl[0]);
            pack_split2(S[2 * s][2],     S[2 * s][3],     ph[1], pl[1]);
            pack_split2(S[2 * s + 1][0], S[2 * s + 1][1], ph[2], pl[2]);
            pack_split2(S[2 * s + 1][2], S[2 * s + 1][3], ph[3], pl[3]);
            const uint32_t vrow =
                (uint32_t)((s * 16 + (lane & 7) + ((lane >> 3) & 1) * 8) * ARS
                           + (lane >> 4) * 16);
            #pragma unroll
            for (int np = 0; np < 4; ++np) {
                const uint32_t voff = vrow + np * 32;
                uint32_t bvh[4], bvl[4];
                LDSM4T(bvh, uS + AVH + voff);
                LDSM4T(bvl, uS + AVL + voff);
                float* cA = O[np * 2];
                float* cB = O[np * 2 + 1];
                MMA_BF16(cA, ph, bvh[0], bvh[1]);
                MMA_BF16(cA, ph, bvl[0], bvl[1]);
                MMA_BF16(cA, pl, bvh[0], bvh[1]);
                MMA_BF16(cB, ph, bvh[2], bvh[3]);
                MMA_BF16(cB, ph, bvl[2], bvl[3]);
                MMA_BF16(cB, pl, bvh[2], bvh[3]);
            }
        }
    }

    // ---- normalize + write split y ----
    const float inv0 = 1.f / l0, inv1 = 1.f / l1;
    const int b = bh >> 4, h = bh & 15;
    const int rg0 = b * Tdim + qt * 128 + w * 16 + r4;
    const size_t base0 = (size_t)rg0 * Cdim + h * HDd;
    #pragma unroll
    for (int j = 0; j < 8; ++j) {
        const int d = j * 8 + c2;
        uint32_t hi, lo;
        pack_split2(O[j][0] * inv0, O[j][1] * inv0, hi, lo);
        *(uint32_t*)&g_y_hi[base0 + d] = hi;
        *(uint32_t*)&g_y_lo[base0 + d] = lo;
        pack_split2(O[j][2] * inv1, O[j][3] * inv1, hi, lo);
        *(uint32_t*)&g_y_hi[base0 + 8 * Cdim + d] = hi;
        *(uint32_t*)&g_y_lo[base0 + 8 * Cdim + d] = lo;
    }
}

// ---------------------------------------------------------------------------
extern "C" void kernel_launch(void* const* d_in, const int* in_sizes, int n_in,
                              void* d_out, int out_size) {
    const float* x      = (const float*)d_in[0];
    const float* w_attn = (const float*)d_in[1];
    const float* b_attn = (const float*)d_in[2];
    const float* w_proj = (const float*)d_in[3];
    const float* b_proj = (const float*)d_in[4];
    float* out = (float*)d_out;

    static bool attr_set = false;
    if (!attr_set) {
        cudaFuncSetAttribute(gemm_bf16x3_kernel,
                             cudaFuncAttributeMaxDynamicSharedMemorySize, GSMEM);
        cudaFuncSetAttribute(attn_mma_kernel,
                             cudaFuncAttributeMaxDynamicSharedMemorySize, ASMEM);
        attr_set = true;
    }

    __nv_bfloat16 *x_hi, *x_lo, *wa_hi, *wa_lo, *wp_hi, *wp_lo, *y_hi, *y_lo;
    cudaGetSymbolAddress((void**)&x_hi, g_x_hi);
    cudaGetSymbolAddress((void**)&x_lo, g_x_lo);
    cudaGetSymbolAddress((void**)&wa_hi, g_wa_hi);
    cudaGetSymbolAddress((void**)&wa_lo, g_wa_lo);
    cudaGetSymbolAddress((void**)&wp_hi, g_wp_hi);
    cudaGetSymbolAddress((void**)&wp_lo, g_wp_lo);
    cudaGetSymbolAddress((void**)&y_hi, g_y_hi);
    cudaGetSymbolAddress((void**)&y_lo, g_y_lo);

    // Prep: split x, transpose+split weights
    prep_x_kernel<<<Mrows * Cdim / (256 * 4), 256>>>(x);
    {
        dim3 ga(N3 / 32, Cdim / 32);
        prep_w_kernel<<<ga, 256>>>(w_attn, wa_hi, wa_lo, Cdim, N3);
        dim3 gp(Cdim / 32, Cdim / 32);
        prep_w_kernel<<<gp, 256>>>(w_proj, wp_hi, wp_lo, Cdim, Cdim);
    }

    // QKV GEMM -> split q/k/v head-major
    dim3 g1(N3 / 128, Mrows / 128);     // 24 x 32
    gemm_bf16x3_kernel<<<g1, 256, GSMEM>>>(x_hi, x_lo, wa_hi, wa_lo,
                                           b_attn, nullptr, 0);

    // Attention (tensor-core)
    dim3 g2(Tdim / 128, Bdim * Hn);     // 16 x 32
    attn_mma_kernel<<<g2, 256, ASMEM>>>();

    // Proj GEMM
    dim3 g3(Cdim / 128, Mrows / 128);   // 8 x 32
    gemm_bf16x3_kernel<<<g3, 256, GSMEM>>>(y_hi, y_lo, wp_hi, wp_lo,
                                           b_proj, out, 1);
}

// round 5
// speedup vs baseline: 2.6802x; 1.0267x over previous
#include <cuda_runtime.h>
#include <cuda_bf16.h>
#include <cstdint>

// Problem constants
#define Bdim 2
#define Tdim 2048
#define Cdim 1024
#define Hn   16
#define HDd  64
#define Mrows (Bdim * Tdim)   // 4096
#define N3    (3 * Cdim)      // 3072

// ---------------------------------------------------------------------------
// Scratch (__device__ globals; allocation-free rule)
// ---------------------------------------------------------------------------
__device__ __nv_bfloat16 g_x_hi[Mrows * Cdim];
__device__ __nv_bfloat16 g_x_lo[Mrows * Cdim];
__device__ __nv_bfloat16 g_wa_hi[N3 * Cdim];     // [N=3072][K=1024]
__device__ __nv_bfloat16 g_wa_lo[N3 * Cdim];
__device__ __nv_bfloat16 g_wp_hi[Cdim * Cdim];   // [N=1024][K=1024]
__device__ __nv_bfloat16 g_wp_lo[Cdim * Cdim];
__device__ __nv_bfloat16 g_y_hi[Mrows * Cdim];   // attn output, [B*T][C]
__device__ __nv_bfloat16 g_y_lo[Mrows * Cdim];

// Split q/k/v, head-major [B*H][T][HD]; q pre-scaled by 1/sqrt(HD)
__device__ __nv_bfloat16 g_qh[Bdim * Hn * Tdim * HDd];
__device__ __nv_bfloat16 g_ql[Bdim * Hn * Tdim * HDd];
__device__ __nv_bfloat16 g_kh[Bdim * Hn * Tdim * HDd];
__device__ __nv_bfloat16 g_kl[Bdim * Hn * Tdim * HDd];
__device__ __nv_bfloat16 g_vh[Bdim * Hn * Tdim * HDd];
__device__ __nv_bfloat16 g_vl[Bdim * Hn * Tdim * HDd];

// ---------------------------------------------------------------------------
// PTX helpers (plain sm_103-safe: mma.sync / ldmatrix / cp.async only)
// ---------------------------------------------------------------------------
__device__ __forceinline__ uint32_t smem_u32(const void* p) {
    uint32_t a;
    asm("{ .reg .u64 t; cvta.to.shared.u64 t, %1; cvt.u32.u64 %0, t; }"
        : "=r"(a) : "l"(p));
    return a;
}

#define LDSM4(r, addr) \
    asm volatile("ldmatrix.sync.aligned.m8n8.x4.shared.b16 {%0,%1,%2,%3}, [%4];" \
        : "=r"((r)[0]), "=r"((r)[1]), "=r"((r)[2]), "=r"((r)[3]) : "r"(addr))

#define LDSM4T(r, addr) \
    asm volatile("ldmatrix.sync.aligned.m8n8.x4.trans.shared.b16 {%0,%1,%2,%3}, [%4];" \
        : "=r"((r)[0]), "=r"((r)[1]), "=r"((r)[2]), "=r"((r)[3]) : "r"(addr))

#define MMA_BF16(c, a, b0, b1) \
    asm volatile("mma.sync.aligned.m16n8k16.row.col.f32.bf16.bf16.f32 " \
        "{%0,%1,%2,%3}, {%4,%5,%6,%7}, {%8,%9}, {%0,%1,%2,%3};" \
        : "+f"((c)[0]), "+f"((c)[1]), "+f"((c)[2]), "+f"((c)[3]) \
        : "r"((a)[0]), "r"((a)[1]), "r"((a)[2]), "r"((a)[3]), "r"(b0), "r"(b1))

#define CP_ASYNC16(dst, src) \
    asm volatile("cp.async.cg.shared.global [%0], [%1], 16;" :: "r"(dst), "l"(src))
#define CP_COMMIT() asm volatile("cp.async.commit_group;")

__device__ __forceinline__ void split_bf16(float v, __nv_bfloat16& h, __nv_bfloat16& l) {
    h = __float2bfloat16(v);
    l = __float2bfloat16(v - __bfloat162float(h));
}

__device__ __forceinline__ void pack_split2(float v0, float v1,
                                            uint32_t& hi, uint32_t& lo) {
    __nv_bfloat16 h0, l0, h1, l1;
    split_bf16(v0, h0, l0);
    split_bf16(v1, h1, l1);
    __nv_bfloat162 hh(h0, h1), ll(l0, l1);
    hi = *(uint32_t*)&hh;
    lo = *(uint32_t*)&ll;
}

// ---------------------------------------------------------------------------
// Prep kernels
// ---------------------------------------------------------------------------
__global__ __launch_bounds__(256) void prep_x_kernel(const float* __restrict__ x) {
    int i = (blockIdx.x * 256 + threadIdx.x) * 4;
    float4 v = *(const float4*)&x[i];
    uint32_t h0, l0, h1, l1;
    pack_split2(v.x, v.y, h0, l0);
    pack_split2(v.z, v.w, h1, l1);
    *(uint32_t*)&g_x_hi[i]     = h0;
    *(uint32_t*)&g_x_hi[i + 2] = h1;
    *(uint32_t*)&g_x_lo[i]     = l0;
    *(uint32_t*)&g_x_lo[i + 2] = l1;
}

// Transpose W [K, N] -> Wt_hi/Wt_lo [N, K] (bf16 split)
__global__ __launch_bounds__(256) void prep_w_kernel(
    const float* __restrict__ W, __nv_bfloat16* __restrict__ Wt_hi,
    __nv_bfloat16* __restrict__ Wt_lo, int K, int N) {
    __shared__ float tile[32][33];
    int n0 = blockIdx.x * 32, k0 = blockIdx.y * 32;
    int tx = threadIdx.x & 31, ty = threadIdx.x >> 5;   // 32 x 8
    #pragma unroll
    for (int r = 0; r < 32; r += 8)
        tile[ty + r][tx] = W[(size_t)(k0 + ty + r) * N + n0 + tx];
    __syncthreads();
    #pragma unroll
    for (int r = 0; r < 32; r += 8) {
        float v = tile[tx][ty + r];
        __nv_bfloat16 h, l; split_bf16(v, h, l);
        size_t o = (size_t)(n0 + ty + r) * K + k0 + tx;
        Wt_hi[o] = h; Wt_lo[o] = l;
    }
}

// ---------------------------------------------------------------------------
// mma.sync bf16x3 GEMM: D[128x128] = A[Mx1024] * B[Nx1024]^T + bias
// Term-pass reordered: each pass issues 16 MMAs to distinct accumulators.
// mode 0: write split bf16 q (x0.125) / k / v head-major.
// mode 1: write fp32 out row-major.
// ---------------------------------------------------------------------------
#define GSTAGE 10240
#define GARR   20480
#define GSMEM  (4 * GARR)   // 81920

__global__ __launch_bounds__(256, 2)
void gemm_bf16x3_kernel(const __nv_bfloat16* __restrict__ Ah,
                        const __nv_bfloat16* __restrict__ Al,
                        const __nv_bfloat16* __restrict__ Bh,
                        const __nv_bfloat16* __restrict__ Bl,
                        const float* __restrict__ bias,
                        float* __restrict__ out, int mode) {
    extern __shared__ __align__(16) char dynsm[];

    const int tid  = threadIdx.x;
    const int lane = tid & 31;
    const int wid  = tid >> 5;
    const int wm   = wid & 3;        // warp row: 32 rows each
    const int wn   = wid >> 2;       // warp col: 64 cols each
    const int n0 = blockIdx.x * 128;
    const int m0 = blockIdx.y * 128;

    const uint32_t uAh = smem_u32(dynsm);
    const uint32_t uAl = uAh + GARR;
    const uint32_t uBh = uAh + 2 * GARR;
    const uint32_t uBl = uAh + 3 * GARR;

    const uint32_t lm_off = (uint32_t)((lane & 15) * 80 + (lane >> 4) * 16);

    float acc[2][8][4] = {};

    auto issue = [&](int ch) {
        const uint32_t soff = (uint32_t)(ch & 1) * GSTAGE;
        const int k0 = ch * 32;
        #pragma unroll
        for (int it = 0; it < 2; ++it) {
            int idx = tid + it * 256;
            int row = idx >> 2;
            int c   = idx & 3;
            uint32_t so = soff + row * 80 + c * 16;
            size_t ga = (size_t)(m0 + row) * Cdim + k0 + c * 8;
            size_t gb = (size_t)(n0 + row) * Cdim + k0 + c * 8;
            CP_ASYNC16(uAh + so, Ah + ga);
            CP_ASYNC16(uAl + so, Al + ga);
            CP_ASYNC16(uBh + so, Bh + gb);
            CP_ASYNC16(uBl + so, Bl + gb);
        }
        CP_COMMIT();
    };

    const int NCH = Cdim / 32;   // 32
    issue(0);
    issue(1);

    for (int ch = 0; ch < NCH; ++ch) {
        if (ch + 1 < NCH) { asm volatile("cp.async.wait_group 1;"); }
        else              { asm volatile("cp.async.wait_group 0;"); }
        __syncthreads();

        const uint32_t soff = (uint32_t)(ch & 1) * GSTAGE;
        #pragma unroll
        for (int k16 = 0; k16 < 2; ++k16) {
            const uint32_t akoff = soff + k16 * 32 + lm_off;
            uint32_t ah[8], al[8], bh[16];
            #pragma unroll
            for (int mt = 0; mt < 2; ++mt) {
                uint32_t rowb = (uint32_t)((wm * 32 + mt * 16) * 80);
                LDSM4(ah + mt * 4, uAh + akoff + rowb);
                LDSM4(al + mt * 4, uAl + akoff + rowb);
            }
            #pragma unroll
            for (int np = 0; np < 4; ++np) {
                uint32_t rowb = (uint32_t)((wn * 64 + np * 16) * 80);
                LDSM4(bh + np * 4, uBh + akoff + rowb);
            }
            // pass 1: hi*hi  (16 MMAs, all distinct accumulators)
            #pragma unroll
            for (int np = 0; np < 4; ++np)
                #pragma unroll
                for (int mt = 0; mt < 2; ++mt)
                    #pragma unroll
                    for (int hf = 0; hf < 2; ++hf)
                        MMA_BF16(acc[mt][np * 2 + hf], ah + mt * 4,
                                 bh[np * 4 + hf], bh[np * 4 + 2 + hf]);
            // pass 2: hi*lo
            #pragma unroll
            for (int np = 0; np < 4; ++np) {
                uint32_t rowb = (uint32_t)((wn * 64 + np * 16) * 80);
                uint32_t bl[4];
                LDSM4(bl, uBl + akoff + rowb);
                #pragma unroll
                for (int mt = 0; mt < 2; ++mt)
                    #pragma unroll
                    for (int hf = 0; hf < 2; ++hf)
                        MMA_BF16(acc[mt][np * 2 + hf], ah + mt * 4,
                                 bl[hf], bl[2 + hf]);
            }
            // pass 3: lo*hi
            #pragma unroll
            for (int np = 0; np < 4; ++np)
                #pragma unroll
                for (int mt = 0; mt < 2; ++mt)
                    #pragma unroll
                    for (int hf = 0; hf < 2; ++hf)
                        MMA_BF16(acc[mt][np * 2 + hf], al + mt * 4,
                                 bh[np * 4 + hf], bh[np * 4 + 2 + hf]);
        }
        __syncthreads();
        if (ch + 2 < NCH) issue(ch + 2);
    }

    // Epilogue
    if (mode == 0) {
        const int ncol0 = n0 + wn * 64;
        const int which = ncol0 >> 10;
        const int hh    = (ncol0 & 1023) >> 6;
        __nv_bfloat16* dh = (which == 0) ? g_qh : ((which == 1) ? g_kh : g_vh);
        __nv_bfloat16* dl = (which == 0) ? g_ql : ((which == 1) ? g_kl : g_vl);
        const float qs = (which == 0) ? 0.125f : 1.0f;
        #pragma unroll
        for (int mt = 0; mt < 2; ++mt) {
            const int rg0 = m0 + wm * 32 + mt * 16 + (lane >> 2);
            const int bb  = rg0 >> 11;
            const int t0  = rg0 & 2047;
            const size_t rbase = (((size_t)bb * Hn + hh) * Tdim + t0) * HDd;
            #pragma unroll
            for (int nt = 0; nt < 8; ++nt) {
                const int d = nt * 8 + (lane & 3) * 2;
                const float2 bv = *(const float2*)&bias[ncol0 + d];
                uint32_t hi, lo;
                pack_split2((acc[mt][nt][0] + bv.x) * qs,
                            (acc[mt][nt][1] + bv.y) * qs, hi, lo);
                *(uint32_t*)&dh[rbase + d] = hi;
                *(uint32_t*)&dl[rbase + d] = lo;
                pack_split2((acc[mt][nt][2] + bv.x) * qs,
                            (acc[mt][nt][3] + bv.y) * qs, hi, lo);
                *(uint32_t*)&dh[rbase + 8 * HDd + d] = hi;
                *(uint32_t*)&dl[rbase + 8 * HDd + d] = lo;
            }
        }
    } else {
        #pragma unroll
        for (int mt = 0; mt < 2; ++mt) {
            const int rg0 = m0 + wm * 32 + mt * 16 + (lane >> 2);
            #pragma unroll
            for (int nt = 0; nt < 8; ++nt) {
                const int ncol = n0 + wn * 64 + nt * 8 + (lane & 3) * 2;
                const float2 bv = *(const float2*)&bias[ncol];
                float2 v0, v1;
                v0.x = acc[mt][nt][0] + bv.x;
                v0.y = acc[mt][nt][1] + bv.y;
                v1.x = acc[mt][nt][2] + bv.x;
                v1.y = acc[mt][nt][3] + bv.y;
                size_t base = (size_t)rg0 * Cdim + ncol;
                *(float2*)&out[base]            = v0;
                *(float2*)&out[base + 8 * Cdim] = v1;
            }
        }
    }
}

// ---------------------------------------------------------------------------
// mma.sync causal flash attention, bf16x3 split for QK^T and PV.
// BQ=128 (8 warps x 16 rows), BKV=64, HD=64. Double-buffered K/V cp.async.
// smem: Q hi/lo @ 0/18432; K/V stages @ 36864 + stage*36864.
// ---------------------------------------------------------------------------
#define ARS 144                      // row stride bytes
#define AQH 0
#define AQL 18432
#define AKV0 36864
#define KVSTG 36864                  // per-stage block (KH,KL,VH,VL x 9216)
#define ASMEM (AKV0 + 2 * KVSTG)     // 110592

__global__ __launch_bounds__(256, 2) void attn_mma_kernel() {
    extern __shared__ __align__(16) char asmem[];
    const int tid = threadIdx.x;
    const int lane = tid & 31;
    const int w = tid >> 5;
    const int qt = gridDim.x - 1 - blockIdx.x;   // heavy tiles first
    const int bh = blockIdx.y;

    const uint32_t uS = smem_u32(asmem);
    const size_t hbase = (size_t)bh * Tdim * HDd;
    const __nv_bfloat16* qh = g_qh + hbase;
    const __nv_bfloat16* ql = g_ql + hbase;
    const __nv_bfloat16* kh = g_kh + hbase;
    const __nv_bfloat16* kl = g_kl + hbase;
    const __nv_bfloat16* vh = g_vh + hbase;
    const __nv_bfloat16* vl = g_vl + hbase;

    auto issue_kv = [&](int kt) {
        const uint32_t sb = uS + AKV0 + (uint32_t)(kt & 1) * KVSTG;
        #pragma unroll
        for (int it = 0; it < 2; ++it) {
            int idx = tid + it * 256;
            int row = idx >> 3, c = idx & 7;
            uint32_t dst = row * ARS + c * 16;
            size_t src = (size_t)(kt * 64 + row) * HDd + c * 8;
            CP_ASYNC16(sb + dst,         kh + src);
            CP_ASYNC16(sb + 9216 + dst,  kl + src);
            CP_ASYNC16(sb + 18432 + dst, vh + src);
            CP_ASYNC16(sb + 27648 + dst, vl + src);
        }
        CP_COMMIT();
    };

    // Q tile load (group 0, committed together with KV stage 0)
    #pragma unroll
    for (int it = 0; it < 4; ++it) {
        int idx = tid + it * 256;
        int row = idx >> 3, c = idx & 7;
        uint32_t dst = row * ARS + c * 16;
        size_t src = (size_t)(qt * 128 + row) * HDd + c * 8;
        CP_ASYNC16(uS + AQH + dst, qh + src);
        CP_ASYNC16(uS + AQL + dst, ql + src);
    }
    issue_kv(0);   // commits Q + KV0 as one group

    const int r4 = lane >> 2;
    const int c2 = (lane & 3) * 2;
    float m0 = -1e30f, m1 = -1e30f, l0 = 0.f, l1 = 0.f;
    float O[8][4] = {};

    const int nkt = 2 * qt + 2;
    for (int kt = 0; kt < nkt; ++kt) {
        const bool more = (kt + 1 < nkt);
        if (more) issue_kv(kt + 1);
        if (more) { asm volatile("cp.async.wait_group 1;"); }
        else      { asm volatile("cp.async.wait_group 0;"); }
        __syncthreads();

        const uint32_t kvb = uS + AKV0 + (uint32_t)(kt & 1) * KVSTG;
        const uint32_t uKH = kvb, uKL = kvb + 9216;
        const uint32_t uVH = kvb + 18432, uVL = kvb + 27648;

        // ---- S = Q K^T (3-term split, term-pass reordered) ----
        float S[8][4] = {};
        #pragma unroll
        for (int k16 = 0; k16 < 4; ++k16) {
            const uint32_t qoff =
                (uint32_t)((w * 16 + (lane & 15)) * ARS + (lane >> 4) * 16 + k16 * 32);
            const uint32_t kfrag =
                (uint32_t)((lane & 15) * ARS + (lane >> 4) * 16 + k16 * 32);
            uint32_t aqh[4], aql[4], bkh[16];
            LDSM4(aqh, uS + AQH + qoff);
            LDSM4(aql, uS + AQL + qoff);
            #pragma unroll
            for (int kp = 0; kp < 4; ++kp)
                LDSM4(bkh + kp * 4, uKH + kfrag + (uint32_t)(kp * 16) * ARS);
            // pass 1: qh*kh (8 distinct accs)
            #pragma unroll
            for (int kp = 0; kp < 4; ++kp)
                #pragma unroll
                for (int hf = 0; hf < 2; ++hf)
                    MMA_BF16(S[kp * 2 + hf], aqh, bkh[kp * 4 + hf], bkh[kp * 4 + 2 + hf]);
            // pass 2: qh*kl
            #pragma unroll
            for (int kp = 0; kp < 4; ++kp) {
                uint32_t bkl[4];
                LDSM4(bkl, uKL + kfrag + (uint32_t)(kp * 16) * ARS);
                #pragma unroll
                for (int hf = 0; hf < 2; ++hf)
                    MMA_BF16(S[kp * 2 + hf], aqh, bkl[hf], bkl[2 + hf]);
            }
            // pass 3: ql*kh
            #pragma unroll
            for (int kp = 0; kp < 4; ++kp)
                #pragma unroll
                for (int hf = 0; hf < 2; ++hf)
                    MMA_BF16(S[kp * 2 + hf], aql, bkh[kp * 4 + hf], bkh[kp * 4 + 2 + hf]);
        }

        // ---- causal mask ----
        const int row0 = qt * 128 + w * 16 + r4;
        if (kt * 64 + 63 > qt * 128 + w * 16) {
            #pragma unroll
            for (int j = 0; j < 8; ++j) {
                const int cb = kt * 64 + j * 8 + c2;
                if (cb     > row0)     S[j][0] = -1e30f;
                if (cb + 1 > row0)     S[j][1] = -1e30f;
                if (cb     > row0 + 8) S[j][2] = -1e30f;
                if (cb + 1 > row0 + 8) S[j][3] = -1e30f;
            }
        }

        // ---- online softmax on fragments ----
        float mt0 = -1e30f, mt1 = -1e30f;
        #pragma unroll
        for (int j = 0; j < 8; ++j) {
            mt0 = fmaxf(mt0, fmaxf(S[j][0], S[j][1]));
            mt1 = fmaxf(mt1, fmaxf(S[j][2], S[j][3]));
        }
        mt0 = fmaxf(mt0, __shfl_xor_sync(0xffffffffu, mt0, 1));
        mt0 = fmaxf(mt0, __shfl_xor_sync(0xffffffffu, mt0, 2));
        mt1 = fmaxf(mt1, __shfl_xor_sync(0xffffffffu, mt1, 1));
        mt1 = fmaxf(mt1, __shfl_xor_sync(0xffffffffu, mt1, 2));
        const float mn0 = fmaxf(m0, mt0);
        const float mn1 = fmaxf(m1, mt1);
        const float sf0 = __expf(m0 - mn0);
        const float sf1 = __expf(m1 - mn1);
        m0 = mn0; m1 = mn1;

        float rs0 = 0.f, rs1 = 0.f;
        #pragma unroll
        for (int j = 0; j < 8; ++j) {
            S[j][0] = __expf(S[j][0] - m0);
            S[j][1] = __expf(S[j][1] - m0);
            S[j][2] = __expf(S[j][2] - m1);
            S[j][3] = __expf(S[j][3] - m1);
            rs0 += S[j][0] + S[j][1];
            rs1 += S[j][2] + S[j][3];
        }
        rs0 += __shfl_xor_sync(0xffffffffu, rs0, 1);
        rs0 += __shfl_xor_sync(0xffffffffu, rs0, 2);
        rs1 += __shfl_xor_sync(0xffffffffu, rs1, 1);
        rs1 += __shfl_xor_sync(0xffffffffu, rs1, 2);
        l0 = l0 * sf0 + rs0;
        l1 = l1 * sf1 + rs1;
        #pragma unroll
        for (int j = 0; j < 8; ++j) {
            O[j][0] *= sf0; O[j][1] *= sf0;
            O[j][2] *= sf1; O[j][3] *= sf1;
        }

        // ---- O += P V (3-term split, term-pass reordered) ----
        #pragma unroll
        for (int s = 0; s < 4; ++s) {
            uint32_t ph[4], pl[4];
            pack_split2(S[2 * s][0],     S[2 * s][1],     ph[0], pl[0]);
            pack_split2(S[2 * s][2],     S[2 * s][3],     ph[1], pl[1]);
            pack_split2(S[2 * s + 1][0], S[2 * s + 1][1], ph[2], pl[2]);
            pack_split2(S[2 * s + 1][2], S[2 * s + 1][3], ph[3], pl[3]);
            const uint32_t vrow =
                (uint32_t)((s * 16 + (lane & 7) + ((lane >> 3) & 1) * 8) * ARS
                           + (lane >> 4) * 16);
            uint32_t bvh[16];
            #pragma unroll
            for (int np = 0; np < 4; ++np)
                LDSM4T(bvh + np * 4, uVH + vrow + np * 32);
            // pass 1: ph*vh (8 distinct accs)
            #pragma unroll
            for (int np = 0; np < 4; ++np) {
                MMA_BF16(O[np * 2],     ph, bvh[np * 4],     bvh[np * 4 + 1]);
                MMA_BF16(O[np * 2 + 1], ph, bvh[np * 4 + 2], bvh[np * 4 + 3]);
            }
            // pass 2: ph*vl
            #pragma unroll
            for (int np = 0; np < 4; ++np) {
                uint32_t bvl[4];
                LDSM4T(bvl, uVL + vrow + np * 32);
                MMA_BF16(O[np * 2],     ph, bvl[0], bvl[1]);
                MMA_BF16(O[np * 2 + 1], ph, bvl[2], bvl[3]);
            }
            // pass 3: pl*vh
            #pragma unroll
            for (int np = 0; np < 4; ++np) {
                MMA_BF16(O[np * 2],     pl, bvh[np * 4],     bvh[np * 4 + 1]);
                MMA_BF16(O[np * 2 + 1], pl, bvh[np * 4 + 2], bvh[np * 4 + 3]);
            }
        }
        __syncthreads();   // frees stage kt&1 for issue(kt+2) next iteration
    }

    // ---- normalize + write split y ----
    const float inv0 = 1.f / l0, inv1 = 1.f / l1;
    const int b = bh >> 4, h = bh & 15;
    const int rg0 = b * Tdim + qt * 128 + w * 16 + r4;
    const size_t base0 = (size_t)rg0 * Cdim + h * HDd;
    #pragma unroll
    for (int j = 0; j < 8; ++j) {
        const int d = j * 8 + c2;
        uint32_t hi, lo;
        pack_split2(O[j][0] * inv0, O[j][1] * inv0, hi, lo);
        *(uint32_t*)&g_y_hi[base0 + d] = hi;
        *(uint32_t*)&g_y_lo[base0 + d] = lo;
        pack_split2(O[j][2] * inv1, O[j][3] * inv1, hi, lo);
        *(uint32_t*)&g_y_hi[base0 + 8 * Cdim + d] = hi;
        *(uint32_t*)&g_y_lo[base0 + 8 * Cdim + d] = lo;
    }
}

// ---------------------------------------------------------------------------
extern "C" void kernel_launch(void* const* d_in, const int* in_sizes, int n_in,
                              void* d_out, int out_size) {
    const float* x      = (const float*)d_in[0];
    const float* w_attn = (const float*)d_in[1];
    const float* b_attn = (const float*)d_in[2];
    const float* w_proj = (const float*)d_in[3];
    const float* b_proj = (const float*)d_in[4];
    float* out = (float*)d_out;

    static bool attr_set = false;
    if (!attr_set) {
        cudaFuncSetAttribute(gemm_bf16x3_kernel,
                             cudaFuncAttributeMaxDynamicSharedMemorySize, GSMEM);
        cudaFuncSetAttribute(attn_mma_kernel,
                             cudaFuncAttributeMaxDynamicSharedMemorySize, ASMEM);
        attr_set = true;
    }

    __nv_bfloat16 *x_hi, *x_lo, *wa_hi, *wa_lo, *wp_hi, *wp_lo, *y_hi, *y_lo;
    cudaGetSymbolAddress((void**)&x_hi, g_x_hi);
    cudaGetSymbolAddress((void**)&x_lo, g_x_lo);
    cudaGetSymbolAddress((void**)&wa_hi, g_wa_hi);
    cudaGetSymbolAddress((void**)&wa_lo, g_wa_lo);
    cudaGetSymbolAddress((void**)&wp_hi, g_wp_hi);
    cudaGetSymbolAddress((void**)&wp_lo, g_wp_lo);
    cudaGetSymbolAddress((void**)&y_hi, g_y_hi);
    cudaGetSymbolAddress((void**)&y_lo, g_y_lo);

    // Prep: split x, transpose+split weights
    prep_x_kernel<<<Mrows * Cdim / (256 * 4), 256>>>(x);
    {
        dim3 ga(N3 / 32, Cdim / 32);
        prep_w_kernel<<<ga, 256>>>(w_attn, wa_hi, wa_lo, Cdim, N3);
        dim3 gp(Cdim / 32, Cdim / 32);
        prep_w_kernel<<<gp, 256>>>(w_proj, wp_hi, wp_lo, Cdim, Cdim);
    }

    // QKV GEMM -> split q/k/v head-major
    dim3 g1(N3 / 128, Mrows / 128);     // 24 x 32
    gemm_bf16x3_kernel<<<g1, 256, GSMEM>>>(x_hi, x_lo, wa_hi, wa_lo,
                                           b_attn, nullptr, 0);

    // Attention (tensor-core, double-buffered K/V)
    dim3 g2(Tdim / 128, Bdim * Hn);     // 16 x 32
    attn_mma_kernel<<<g2, 256, ASMEM>>>();

    // Proj GEMM
    dim3 g3(Cdim / 128, Mrows / 128);   // 8 x 32
    gemm_bf16x3_kernel<<<g3, 256, GSMEM>>>(y_hi, y_lo, wp_hi, wp_lo,
                                           b_proj, out, 1);
}

// round 6
// speedup vs baseline: 2.8582x; 1.0664x over previous
#include <cuda_runtime.h>
#include <cuda_bf16.h>
#include <cstdint>

// Problem constants
#define Bdim 2
#define Tdim 2048
#define Cdim 1024
#define Hn   16
#define HDd  64
#define Mrows (Bdim * Tdim)   // 4096
#define N3    (3 * Cdim)      // 3072

// ---------------------------------------------------------------------------
// Scratch (__device__ globals; allocation-free rule)
// ---------------------------------------------------------------------------
__device__ __nv_bfloat16 g_x_hi[Mrows * Cdim];
__device__ __nv_bfloat16 g_x_lo[Mrows * Cdim];
__device__ __nv_bfloat16 g_wa_hi[N3 * Cdim];     // [N=3072][K=1024]
__device__ __nv_bfloat16 g_wa_lo[N3 * Cdim];
__device__ __nv_bfloat16 g_wp_hi[Cdim * Cdim];   // [N=1024][K=1024]
__device__ __nv_bfloat16 g_wp_lo[Cdim * Cdim];
__device__ __nv_bfloat16 g_y_hi[Mrows * Cdim];   // attn output, [B*T][C]
__device__ __nv_bfloat16 g_y_lo[Mrows * Cdim];

// Split q/k/v, head-major [B*H][T][HD]; q pre-scaled by 1/sqrt(HD)
__device__ __nv_bfloat16 g_qh[Bdim * Hn * Tdim * HDd];
__device__ __nv_bfloat16 g_ql[Bdim * Hn * Tdim * HDd];
__device__ __nv_bfloat16 g_kh[Bdim * Hn * Tdim * HDd];
__device__ __nv_bfloat16 g_kl[Bdim * Hn * Tdim * HDd];
__device__ __nv_bfloat16 g_vh[Bdim * Hn * Tdim * HDd];
__device__ __nv_bfloat16 g_vl[Bdim * Hn * Tdim * HDd];

// ---------------------------------------------------------------------------
// PTX helpers (plain sm_103-safe: mma.sync / ldmatrix / cp.async only)
// ---------------------------------------------------------------------------
__device__ __forceinline__ uint32_t smem_u32(const void* p) {
    uint32_t a;
    asm("{ .reg .u64 t; cvta.to.shared.u64 t, %1; cvt.u32.u64 %0, t; }"
        : "=r"(a) : "l"(p));
    return a;
}

#define LDSM4(r, addr) \
    asm volatile("ldmatrix.sync.aligned.m8n8.x4.shared.b16 {%0,%1,%2,%3}, [%4];" \
        : "=r"((r)[0]), "=r"((r)[1]), "=r"((r)[2]), "=r"((r)[3]) : "r"(addr))

#define LDSM4T(r, addr) \
    asm volatile("ldmatrix.sync.aligned.m8n8.x4.trans.shared.b16 {%0,%1,%2,%3}, [%4];" \
        : "=r"((r)[0]), "=r"((r)[1]), "=r"((r)[2]), "=r"((r)[3]) : "r"(addr))

#define MMA_BF16(c, a, b0, b1) \
    asm volatile("mma.sync.aligned.m16n8k16.row.col.f32.bf16.bf16.f32 " \
        "{%0,%1,%2,%3}, {%4,%5,%6,%7}, {%8,%9}, {%0,%1,%2,%3};" \
        : "+f"((c)[0]), "+f"((c)[1]), "+f"((c)[2]), "+f"((c)[3]) \
        : "r"((a)[0]), "r"((a)[1]), "r"((a)[2]), "r"((a)[3]), "r"(b0), "r"(b1))

#define CP_ASYNC16(dst, src) \
    asm volatile("cp.async.cg.shared.global [%0], [%1], 16;" :: "r"(dst), "l"(src))
#define CP_COMMIT() asm volatile("cp.async.commit_group;")

__device__ __forceinline__ void split_bf16(float v, __nv_bfloat16& h, __nv_bfloat16& l) {
    h = __float2bfloat16(v);
    l = __float2bfloat16(v - __bfloat162float(h));
}

__device__ __forceinline__ void pack_split2(float v0, float v1,
                                            uint32_t& hi, uint32_t& lo) {
    __nv_bfloat16 h0, l0, h1, l1;
    split_bf16(v0, h0, l0);
    split_bf16(v1, h1, l1);
    __nv_bfloat162 hh(h0, h1), ll(l0, l1);
    hi = *(uint32_t*)&hh;
    lo = *(uint32_t*)&ll;
}

// ---------------------------------------------------------------------------
// Prep kernels
// ---------------------------------------------------------------------------
__global__ __launch_bounds__(256) void prep_x_kernel(const float* __restrict__ x) {
    int i = (blockIdx.x * 256 + threadIdx.x) * 4;
    float4 v = *(const float4*)&x[i];
    uint32_t h0, l0, h1, l1;
    pack_split2(v.x, v.y, h0, l0);
    pack_split2(v.z, v.w, h1, l1);
    *(uint32_t*)&g_x_hi[i]     = h0;
    *(uint32_t*)&g_x_hi[i + 2] = h1;
    *(uint32_t*)&g_x_lo[i]     = l0;
    *(uint32_t*)&g_x_lo[i + 2] = l1;
}

// Transpose W [K, N] -> Wt_hi/Wt_lo [N, K] (bf16 split)
__global__ __launch_bounds__(256) void prep_w_kernel(
    const float* __restrict__ W, __nv_bfloat16* __restrict__ Wt_hi,
    __nv_bfloat16* __restrict__ Wt_lo, int K, int N) {
    __shared__ float tile[32][33];
    int n0 = blockIdx.x * 32, k0 = blockIdx.y * 32;
    int tx = threadIdx.x & 31, ty = threadIdx.x >> 5;   // 32 x 8
    #pragma unroll
    for (int r = 0; r < 32; r += 8)
        tile[ty + r][tx] = W[(size_t)(k0 + ty + r) * N + n0 + tx];
    __syncthreads();
    #pragma unroll
    for (int r = 0; r < 32; r += 8) {
        float v = tile[tx][ty + r];
        __nv_bfloat16 h, l; split_bf16(v, h, l);
        size_t o = (size_t)(n0 + ty + r) * K + k0 + tx;
        Wt_hi[o] = h; Wt_lo[o] = l;
    }
}

// ---------------------------------------------------------------------------
// mma.sync bf16x3 GEMM: D[128x128] = A[Mx1024] * B[Nx1024]^T + bias
// 3-stage cp.async pipeline (prefetch depth 2), BK=32.
// Packed-swizzled smem: two 64B logical rows per 128B smem row,
// chunk ^= (m>>1)&3  -> conflict-free ldmatrix, zero padding.
// Stage = 4 arrays x 8KB = 32KB; 3 stages = 96KB; occ 2.
// mode 0: write split bf16 q (x0.125) / k / v head-major.
// mode 1: write fp32 out row-major.
// ---------------------------------------------------------------------------
#define GARR8  8192                 // one array (128x32 bf16 packed)
#define GSTG   (4 * GARR8)          // 32768 per stage
#define GSMEM  (3 * GSTG)           // 98304

// packed smem byte offset for logical row m (0..127), 16B-chunk c (0..3)
__device__ __forceinline__ uint32_t pk_off(int m, int c) {
    return (uint32_t)((m >> 1) * 128 + (m & 1) * 64 + ((c ^ ((m >> 1) & 3)) << 4));
}

__global__ __launch_bounds__(256, 2)
void gemm_bf16x3_kernel(const __nv_bfloat16* __restrict__ Ah,
                        const __nv_bfloat16* __restrict__ Al,
                        const __nv_bfloat16* __restrict__ Bh,
                        const __nv_bfloat16* __restrict__ Bl,
                        const float* __restrict__ bias,
                        float* __restrict__ out, int mode) {
    extern __shared__ __align__(16) char dynsm[];

    const int tid  = threadIdx.x;
    const int lane = tid & 31;
    const int wid  = tid >> 5;
    const int wm   = wid & 3;        // warp row: 32 rows each
    const int wn   = wid >> 2;       // warp col: 64 cols each
    const int n0 = blockIdx.x * 128;
    const int m0 = blockIdx.y * 128;

    const uint32_t uS = smem_u32(dynsm);

    float acc[2][8][4] = {};

    auto issue = [&](int ch) {
        const uint32_t sb = uS + (uint32_t)(ch % 3) * GSTG;
        const int k0 = ch * 32;
        #pragma unroll
        for (int it = 0; it < 2; ++it) {
            int idx = tid + it * 256;
            int m = idx >> 2;
            int c = idx & 3;
            uint32_t so = pk_off(m, c);
            size_t ga = (size_t)(m0 + m) * Cdim + k0 + c * 8;
            size_t gb = (size_t)(n0 + m) * Cdim + k0 + c * 8;
            CP_ASYNC16(sb + so,             Ah + ga);
            CP_ASYNC16(sb + GARR8 + so,     Al + ga);
            CP_ASYNC16(sb + 2 * GARR8 + so, Bh + gb);
            CP_ASYNC16(sb + 3 * GARR8 + so, Bl + gb);
        }
        CP_COMMIT();
    };

    // per-lane ldmatrix address precomputes (row part + xor key)
    uint32_t arow[2], axor[2], brow[4], bxor[4];
    #pragma unroll
    for (int mt = 0; mt < 2; ++mt) {
        int m = wm * 32 + mt * 16 + (lane & 15);
        arow[mt] = (uint32_t)((m >> 1) * 128 + (m & 1) * 64);
        axor[mt] = (uint32_t)((m >> 1) & 3);
    }
    #pragma unroll
    for (int np = 0; np < 4; ++np) {
        int n = wn * 64 + np * 16 + (lane & 15);
        brow[np] = (uint32_t)((n >> 1) * 128 + (n & 1) * 64);
        bxor[np] = (uint32_t)((n >> 1) & 3);
    }
    const int chalf = lane >> 4;   // which 16B chunk within the k16

    const int NCH = Cdim / 32;   // 32
    issue(0);
    issue(1);

    for (int ch = 0; ch < NCH; ++ch) {
        if (ch + 1 < NCH) { asm volatile("cp.async.wait_group 1;"); }
        else              { asm volatile("cp.async.wait_group 0;"); }
        __syncthreads();
        if (ch + 2 < NCH) issue(ch + 2);

        const uint32_t sb  = uS + (uint32_t)(ch % 3) * GSTG;
        const uint32_t sAh = sb, sAl = sb + GARR8;
        const uint32_t sBh = sb + 2 * GARR8, sBl = sb + 3 * GARR8;

        #pragma unroll
        for (int kk = 0; kk < 2; ++kk) {
            const int cix = kk * 2 + chalf;     // chunk index 0..3
            uint32_t ah[8], al[8], bh[16];
            #pragma unroll
            for (int mt = 0; mt < 2; ++mt) {
                uint32_t ao = arow[mt] + (uint32_t)((cix ^ axor[mt]) << 4);
                LDSM4(ah + mt * 4, sAh + ao);
                LDSM4(al + mt * 4, sAl + ao);
            }
            #pragma unroll
            for (int np = 0; np < 4; ++np) {
                uint32_t bo = brow[np] + (uint32_t)((cix ^ bxor[np]) << 4);
                LDSM4(bh + np * 4, sBh + bo);
            }
            // pass 1: hi*hi (16 distinct accumulators)
            #pragma unroll
            for (int np = 0; np < 4; ++np)
                #pragma unroll
                for (int mt = 0; mt < 2; ++mt)
                    #pragma unroll
                    for (int hf = 0; hf < 2; ++hf)
                        MMA_BF16(acc[mt][np * 2 + hf], ah + mt * 4,
                                 bh[np * 4 + hf], bh[np * 4 + 2 + hf]);
            // pass 2: hi*lo
            #pragma unroll
            for (int np = 0; np < 4; ++np) {
                uint32_t bo = brow[np] + (uint32_t)((cix ^ bxor[np]) << 4);
                uint32_t bl[4];
                LDSM4(bl, sBl + bo);
                #pragma unroll
                for (int mt = 0; mt < 2; ++mt)
                    #pragma unroll
                    for (int hf = 0; hf < 2; ++hf)
                        MMA_BF16(acc[mt][np * 2 + hf], ah + mt * 4,
                                 bl[hf], bl[2 + hf]);
            }
            // pass 3: lo*hi
            #pragma unroll
            for (int np = 0; np < 4; ++np)
                #pragma unroll
                for (int mt = 0; mt < 2; ++mt)
                    #pragma unroll
                    for (int hf = 0; hf < 2; ++hf)
                        MMA_BF16(acc[mt][np * 2 + hf], al + mt * 4,
                                 bh[np * 4 + hf], bh[np * 4 + 2 + hf]);
        }
    }

    // Epilogue
    if (mode == 0) {
        const int ncol0 = n0 + wn * 64;
        const int which = ncol0 >> 10;
        const int hh    = (ncol0 & 1023) >> 6;
        __nv_bfloat16* dh = (which == 0) ? g_qh : ((which == 1) ? g_kh : g_vh);
        __nv_bfloat16* dl = (which == 0) ? g_ql : ((which == 1) ? g_kl : g_vl);
        const float qs = (which == 0) ? 0.125f : 1.0f;
        #pragma unroll
        for (int mt = 0; mt < 2; ++mt) {
            const int rg0 = m0 + wm * 32 + mt * 16 + (lane >> 2);
            const int bb  = rg0 >> 11;
            const int t0  = rg0 & 2047;
            const size_t rbase = (((size_t)bb * Hn + hh) * Tdim + t0) * HDd;
            #pragma unroll
            for (int nt = 0; nt < 8; ++nt) {
                const int d = nt * 8 + (lane & 3) * 2;
                const float2 bv = *(const float2*)&bias[ncol0 + d];
                uint32_t hi, lo;
                pack_split2((acc[mt][nt][0] + bv.x) * qs,
                            (acc[mt][nt][1] + bv.y) * qs, hi, lo);
                *(uint32_t*)&dh[rbase + d] = hi;
                *(uint32_t*)&dl[rbase + d] = lo;
                pack_split2((acc[mt][nt][2] + bv.x) * qs,
                            (acc[mt][nt][3] + bv.y) * qs, hi, lo);
                *(uint32_t*)&dh[rbase + 8 * HDd + d] = hi;
                *(uint32_t*)&dl[rbase + 8 * HDd + d] = lo;
            }
        }
    } else {
        #pragma unroll
        for (int mt = 0; mt < 2; ++mt) {
            const int rg0 = m0 + wm * 32 + mt * 16 + (lane >> 2);
            #pragma unroll
            for (int nt = 0; nt < 8; ++nt) {
                const int ncol = n0 + wn * 64 + nt * 8 + (lane & 3) * 2;
                const float2 bv = *(const float2*)&bias[ncol];
                float2 v0, v1;
                v0.x = acc[mt][nt][0] + bv.x;
                v0.y = acc[mt][nt][1] + bv.y;
                v1.x = acc[mt][nt][2] + bv.x;
                v1.y = acc[mt][nt][3] + bv.y;
                size_t base = (size_t)rg0 * Cdim + ncol;
                *(float2*)&out[base]            = v0;
                *(float2*)&out[base + 8 * Cdim] = v1;
            }
        }
    }
}

// ---------------------------------------------------------------------------
// mma.sync causal flash attention, bf16x3 split for QK^T and PV.
// BQ=128 (8 warps x 16 rows), BKV=64, HD=64. Double-buffered K/V cp.async.
// ---------------------------------------------------------------------------
#define ARS 144                      // row stride bytes
#define AQH 0
#define AQL 18432
#define AKV0 36864
#define KVSTG 36864                  // per-stage block (KH,KL,VH,VL x 9216)
#define ASMEM (AKV0 + 2 * KVSTG)     // 110592

__global__ __launch_bounds__(256, 2) void attn_mma_kernel() {
    extern __shared__ __align__(16) char asmem[];
    const int tid = threadIdx.x;
    const int lane = tid & 31;
    const int w = tid >> 5;
    const int qt = gridDim.x - 1 - blockIdx.x;   // heavy tiles first
    const int bh = blockIdx.y;

    const uint32_t uS = smem_u32(asmem);
    const size_t hbase = (size_t)bh * Tdim * HDd;
    const __nv_bfloat16* qh = g_qh + hbase;
    const __nv_bfloat16* ql = g_ql + hbase;
    const __nv_bfloat16* kh = g_kh + hbase;
    const __nv_bfloat16* kl = g_kl + hbase;
    const __nv_bfloat16* vh = g_vh + hbase;
    const __nv_bfloat16* vl = g_vl + hbase;

    auto issue_kv = [&](int kt) {
        const uint32_t sb = uS + AKV0 + (uint32_t)(kt & 1) * KVSTG;
        #pragma unroll
        for (int it = 0; it < 2; ++it) {
            int idx = tid + it * 256;
            int row = idx >> 3, c = idx & 7;
            uint32_t dst = row * ARS + c * 16;
            size_t src = (size_t)(kt * 64 + row) * HDd + c * 8;
            CP_ASYNC16(sb + dst,         kh + src);
            CP_ASYNC16(sb + 9216 + dst,  kl + src);
            CP_ASYNC16(sb + 18432 + dst, vh + src);
            CP_ASYNC16(sb + 27648 + dst, vl + src);
        }
        CP_COMMIT();
    };

    // Q tile load (committed with KV stage 0)
    #pragma unroll
    for (int it = 0; it < 4; ++it) {
        int idx = tid + it * 256;
        int row = idx >> 3, c = idx & 7;
        uint32_t dst = row * ARS + c * 16;
        size_t src = (size_t)(qt * 128 + row) * HDd + c * 8;
        CP_ASYNC16(uS + AQH + dst, qh + src);
        CP_ASYNC16(uS + AQL + dst, ql + src);
    }
    issue_kv(0);

    const int r4 = lane >> 2;
    const int c2 = (lane & 3) * 2;
    float m0 = -1e30f, m1 = -1e30f, l0 = 0.f, l1 = 0.f;
    float O[8][4] = {};

    const int nkt = 2 * qt + 2;
    for (int kt = 0; kt < nkt; ++kt) {
        const bool more = (kt + 1 < nkt);
        if (more) issue_kv(kt + 1);
        if (more) { asm volatile("cp.async.wait_group 1;"); }
        else      { asm volatile("cp.async.wait_group 0;"); }
        __syncthreads();

        const uint32_t kvb = uS + AKV0 + (uint32_t)(kt & 1) * KVSTG;
        const uint32_t uKH = kvb, uKL = kvb + 9216;
        const uint32_t uVH = kvb + 18432, uVL = kvb + 27648;

        // ---- S = Q K^T (3-term split, term-pass reordered) ----
        float S[8][4] = {};
        #pragma unroll
        for (int k16 = 0; k16 < 4; ++k16) {
            const uint32_t qoff =
                (uint32_t)((w * 16 + (lane & 15)) * ARS + (lane >> 4) * 16 + k16 * 32);
            const uint32_t kfrag =
                (uint32_t)((lane & 15) * ARS + (lane >> 4) * 16 + k16 * 32);
            uint32_t aqh[4], aql[4], bkh[16];
            LDSM4(aqh, uS + AQH + qoff);
            LDSM4(aql, uS + AQL + qoff);
            #pragma unroll
            for (int kp = 0; kp < 4; ++kp)
                LDSM4(bkh + kp * 4, uKH + kfrag + (uint32_t)(kp * 16) * ARS);
            #pragma unroll
            for (int kp = 0; kp < 4; ++kp)
                #pragma unroll
                for (int hf = 0; hf < 2; ++hf)
                    MMA_BF16(S[kp * 2 + hf], aqh, bkh[kp * 4 + hf], bkh[kp * 4 + 2 + hf]);
            #pragma unroll
            for (int kp = 0; kp < 4; ++kp) {
                uint32_t bkl[4];
                LDSM4(bkl, uKL + kfrag + (uint32_t)(kp * 16) * ARS);
                #pragma unroll
                for (int hf = 0; hf < 2; ++hf)
                    MMA_BF16(S[kp * 2 + hf], aqh, bkl[hf], bkl[2 + hf]);
            }
            #pragma unroll
            for (int kp = 0; kp < 4; ++kp)
                #pragma unroll
                for (int hf = 0; hf < 2; ++hf)
                    MMA_BF16(S[kp * 2 + hf], aql, bkh[kp * 4 + hf], bkh[kp * 4 + 2 + hf]);
        }

        // ---- causal mask ----
        const int row0 = qt * 128 + w * 16 + r4;
        if (kt * 64 + 63 > qt * 128 + w * 16) {
            #pragma unroll
            for (int j = 0; j < 8; ++j) {
                const int cb = kt * 64 + j * 8 + c2;
                if (cb     > row0)     S[j][0] = -1e30f;
                if (cb + 1 > row0)     S[j][1] = -1e30f;
                if (cb     > row0 + 8) S[j][2] = -1e30f;
                if (cb + 1 > row0 + 8) S[j][3] = -1e30f;
            }
        }

        // ---- online softmax on fragments ----
        float mt0 = -1e30f, mt1 = -1e30f;
        #pragma unroll
        for (int j = 0; j < 8; ++j) {
            mt0 = fmaxf(mt0, fmaxf(S[j][0], S[j][1]));
            mt1 = fmaxf(mt1, fmaxf(S[j][2], S[j][3]));
        }
        mt0 = fmaxf(mt0, __shfl_xor_sync(0xffffffffu, mt0, 1));
        mt0 = fmaxf(mt0, __shfl_xor_sync(0xffffffffu, mt0, 2));
        mt1 = fmaxf(mt1, __shfl_xor_sync(0xffffffffu, mt1, 1));
        mt1 = fmaxf(mt1, __shfl_xor_sync(0xffffffffu, mt1, 2));
        const float mn0 = fmaxf(m0, mt0);
        const float mn1 = fmaxf(m1, mt1);
        const float sf0 = __expf(m0 - mn0);
        const float sf1 = __expf(m1 - mn1);
        m0 = mn0; m1 = mn1;

        float rs0 = 0.f, rs1 = 0.f;
        #pragma unroll
        for (int j = 0; j < 8; ++j) {
            S[j][0] = __expf(S[j][0] - m0);
            S[j][1] = __expf(S[j][1] - m0);
            S[j][2] = __expf(S[j][2] - m1);
            S[j][3] = __expf(S[j][3] - m1);
            rs0 += S[j][0] + S[j][1];
            rs1 += S[j][2] + S[j][3];
        }
        rs0 += __shfl_xor_sync(0xffffffffu, rs0, 1);
        rs0 += __shfl_xor_sync(0xffffffffu, rs0, 2);
        rs1 += __shfl_xor_sync(0xffffffffu, rs1, 1);
        rs1 += __shfl_xor_sync(0xffffffffu, rs1, 2);
        l0 = l0 * sf0 + rs0;
        l1 = l1 * sf1 + rs1;
        #pragma unroll
        for (int j = 0; j < 8; ++j) {
            O[j][0] *= sf0; O[j][1] *= sf0;
            O[j][2] *= sf1; O[j][3] *= sf1;
        }

        // ---- O += P V (3-term split, term-pass reordered) ----
        #pragma unroll
        for (int s = 0; s < 4; ++s) {
            uint32_t ph[4], pl[4];
            pack_split2(S[2 * s][0],     S[2 * s][1],     ph[0], pl[0]);
            pack_split2(S[2 * s][2],     S[2 * s][3],     ph[1], pl[1]);
            pack_split2(S[2 * s + 1][0], S[2 * s + 1][1], ph[2], pl[2]);
            pack_split2(S[2 * s + 1][2], S[2 * s + 1][3], ph[3], pl[3]);
            const uint32_t vrow =
                (uint32_t)((s * 16 + (lane & 7) + ((lane >> 3) & 1) * 8) * ARS
                           + (lane >> 4) * 16);
            uint32_t bvh[16];
            #pragma unroll
            for (int np = 0; np < 4; ++np)
                LDSM4T(bvh + np * 4, uVH + vrow + np * 32);
            #pragma unroll
            for (int np = 0; np < 4; ++np) {
                MMA_BF16(O[np * 2],     ph, bvh[np * 4],     bvh[np * 4 + 1]);
                MMA_BF16(O[np * 2 + 1], ph, bvh[np * 4 + 2], bvh[np * 4 + 3]);
            }
            #pragma unroll
            for (int np = 0; np < 4; ++np) {
                uint32_t bvl[4];
                LDSM4T(bvl, uVL + vrow + np * 32);
                MMA_BF16(O[np * 2],     ph, bvl[0], bvl[1]);
                MMA_BF16(O[np * 2 + 1], ph, bvl[2], bvl[3]);
            }
            #pragma unroll
            for (int np = 0; np < 4; ++np) {
                MMA_BF16(O[np * 2],     pl, bvh[np * 4],     bvh[np * 4 + 1]);
                MMA_BF16(O[np * 2 + 1], pl, bvh[np * 4 + 2], bvh[np * 4 + 3]);
            }
        }
        __syncthreads();
    }

    // ---- normalize + write split y ----
    const float inv0 = 1.f / l0, inv1 = 1.f / l1;
    const int b = bh >> 4, h = bh & 15;
    const int rg0 = b * Tdim + qt * 128 + w * 16 + r4;
    const size_t base0 = (size_t)rg0 * Cdim + h * HDd;
    #pragma unroll
    for (int j = 0; j < 8; ++j) {
        const int d = j * 8 + c2;
        uint32_t hi, lo;
        pack_split2(O[j][0] * inv0, O[j][1] * inv0, hi, lo);
        *(uint32_t*)&g_y_hi[base0 + d] = hi;
        *(uint32_t*)&g_y_lo[base0 + d] = lo;
        pack_split2(O[j][2] * inv1, O[j][3] * inv1, hi, lo);
        *(uint32_t*)&g_y_hi[base0 + 8 * Cdim + d] = hi;
        *(uint32_t*)&g_y_lo[base0 + 8 * Cdim + d] = lo;
    }
}

// ---------------------------------------------------------------------------
extern "C" void kernel_launch(void* const* d_in, const int* in_sizes, int n_in,
                              void* d_out, int out_size) {
    const float* x      = (const float*)d_in[0];
    const float* w_attn = (const float*)d_in[1];
    const float* b_attn = (const float*)d_in[2];
    const float* w_proj = (const float*)d_in[3];
    const float* b_proj = (const float*)d_in[4];
    float* out = (float*)d_out;

    static bool attr_set = false;
    if (!attr_set) {
        cudaFuncSetAttribute(gemm_bf16x3_kernel,
                             cudaFuncAttributeMaxDynamicSharedMemorySize, GSMEM);
        cudaFuncSetAttribute(attn_mma_kernel,
                             cudaFuncAttributeMaxDynamicSharedMemorySize, ASMEM);
        attr_set = true;
    }

    __nv_bfloat16 *x_hi, *x_lo, *wa_hi, *wa_lo, *wp_hi, *wp_lo, *y_hi, *y_lo;
    cudaGetSymbolAddress((void**)&x_hi, g_x_hi);
    cudaGetSymbolAddress((void**)&x_lo, g_x_lo);
    cudaGetSymbolAddress((void**)&wa_hi, g_wa_hi);
    cudaGetSymbolAddress((void**)&wa_lo, g_wa_lo);
    cudaGetSymbolAddress((void**)&wp_hi, g_wp_hi);
    cudaGetSymbolAddress((void**)&wp_lo, g_wp_lo);
    cudaGetSymbolAddress((void**)&y_hi, g_y_hi);
    cudaGetSymbolAddress((void**)&y_lo, g_y_lo);

    // Prep: split x, transpose+split weights
    prep_x_kernel<<<Mrows * Cdim / (256 * 4), 256>>>(x);
    {
        dim3 ga(N3 / 32, Cdim / 32);
        prep_w_kernel<<<ga, 256>>>(w_attn, wa_hi, wa_lo, Cdim, N3);
        dim3 gp(Cdim / 32, Cdim / 32);
        prep_w_kernel<<<gp, 256>>>(w_proj, wp_hi, wp_lo, Cdim, Cdim);
    }

    // QKV GEMM -> split q/k/v head-major
    dim3 g1(N3 / 128, Mrows / 128);     // 24 x 32
    gemm_bf16x3_kernel<<<g1, 256, GSMEM>>>(x_hi, x_lo, wa_hi, wa_lo,
                                           b_attn, nullptr, 0);

    // Attention (tensor-core, double-buffered K/V)
    dim3 g2(Tdim / 128, Bdim * Hn);     // 16 x 32
    attn_mma_kernel<<<g2, 256, ASMEM>>>();

    // Proj GEMM
    dim3 g3(Cdim / 128, Mrows / 128);   // 8 x 32
    gemm_bf16x3_kernel<<<g3, 256, GSMEM>>>(y_hi, y_lo, wp_hi, wp_lo,
                                           b_proj, out, 1);
}

// round 7
// speedup vs baseline: 3.4139x; 1.1944x over previous
#include <cuda_runtime.h>
#include <cuda_bf16.h>
#include <cuda_fp16.h>
#include <cstdint>

// Problem constants
#define Bdim 2
#define Tdim 2048
#define Cdim 1024
#define Hn   16
#define HDd  64
#define Mrows (Bdim * Tdim)   // 4096
#define N3    (3 * Cdim)      // 3072

// ---------------------------------------------------------------------------
// Scratch (__device__ globals; allocation-free rule)
// ---------------------------------------------------------------------------
__device__ __half g_x_hi[Mrows * Cdim];
__device__ __half g_x_lo[Mrows * Cdim];
__device__ __half g_wa[N3 * Cdim];        // [N=3072][K=1024], fp16 single
__device__ __half g_wp[Cdim * Cdim];      // [N=1024][K=1024], fp16 single
__device__ __half g_y_hi[Mrows * Cdim];   // attn output, [B*T][C], fp16 split
__device__ __half g_y_lo[Mrows * Cdim];

// Split q/k/v (bf16, 3-term path), head-major [B*H][T][HD]; q pre-scaled
__device__ __nv_bfloat16 g_qh[Bdim * Hn * Tdim * HDd];
__device__ __nv_bfloat16 g_ql[Bdim * Hn * Tdim * HDd];
__device__ __nv_bfloat16 g_kh[Bdim * Hn * Tdim * HDd];
__device__ __nv_bfloat16 g_kl[Bdim * Hn * Tdim * HDd];
__device__ __nv_bfloat16 g_vh[Bdim * Hn * Tdim * HDd];
__device__ __nv_bfloat16 g_vl[Bdim * Hn * Tdim * HDd];

// ---------------------------------------------------------------------------
// PTX helpers (plain sm_103-safe)
// ---------------------------------------------------------------------------
__device__ __forceinline__ uint32_t smem_u32(const void* p) {
    uint32_t a;
    asm("{ .reg .u64 t; cvta.to.shared.u64 t, %1; cvt.u32.u64 %0, t; }"
        : "=r"(a) : "l"(p));
    return a;
}

#define LDSM4(r, addr) \
    asm volatile("ldmatrix.sync.aligned.m8n8.x4.shared.b16 {%0,%1,%2,%3}, [%4];" \
        : "=r"((r)[0]), "=r"((r)[1]), "=r"((r)[2]), "=r"((r)[3]) : "r"(addr))

#define LDSM4T(r, addr) \
    asm volatile("ldmatrix.sync.aligned.m8n8.x4.trans.shared.b16 {%0,%1,%2,%3}, [%4];" \
        : "=r"((r)[0]), "=r"((r)[1]), "=r"((r)[2]), "=r"((r)[3]) : "r"(addr))

#define MMA_BF16(c, a, b0, b1) \
    asm volatile("mma.sync.aligned.m16n8k16.row.col.f32.bf16.bf16.f32 " \
        "{%0,%1,%2,%3}, {%4,%5,%6,%7}, {%8,%9}, {%0,%1,%2,%3};" \
        : "+f"((c)[0]), "+f"((c)[1]), "+f"((c)[2]), "+f"((c)[3]) \
        : "r"((a)[0]), "r"((a)[1]), "r"((a)[2]), "r"((a)[3]), "r"(b0), "r"(b1))

#define MMA_F16(c, a, b0, b1) \
    asm volatile("mma.sync.aligned.m16n8k16.row.col.f32.f16.f16.f32 " \
        "{%0,%1,%2,%3}, {%4,%5,%6,%7}, {%8,%9}, {%0,%1,%2,%3};" \
        : "+f"((c)[0]), "+f"((c)[1]), "+f"((c)[2]), "+f"((c)[3]) \
        : "r"((a)[0]), "r"((a)[1]), "r"((a)[2]), "r"((a)[3]), "r"(b0), "r"(b1))

#define CP_ASYNC16(dst, src) \
    asm volatile("cp.async.cg.shared.global [%0], [%1], 16;" :: "r"(dst), "l"(src))
#define CP_COMMIT() asm volatile("cp.async.commit_group;")

__device__ __forceinline__ void split_bf16(float v, __nv_bfloat16& h, __nv_bfloat16& l) {
    h = __float2bfloat16(v);
    l = __float2bfloat16(v - __bfloat162float(h));
}

__device__ __forceinline__ void pack_split2(float v0, float v1,
                                            uint32_t& hi, uint32_t& lo) {
    __nv_bfloat16 h0, l0, h1, l1;
    split_bf16(v0, h0, l0);
    split_bf16(v1, h1, l1);
    __nv_bfloat162 hh(h0, h1), ll(l0, l1);
    hi = *(uint32_t*)&hh;
    lo = *(uint32_t*)&ll;
}

// fp16 split pack
__device__ __forceinline__ void pack_split2h(float v0, float v1,
                                             uint32_t& hi, uint32_t& lo) {
    __half h0 = __float2half_rn(v0);
    __half l0 = __float2half_rn(v0 - __half2float(h0));
    __half h1 = __float2half_rn(v1);
    __half l1 = __float2half_rn(v1 - __half2float(h1));
    __half2 hh(h0, h1), ll(l0, l1);
    hi = *(uint32_t*)&hh;
    lo = *(uint32_t*)&ll;
}

// ---------------------------------------------------------------------------
// Prep kernels
// ---------------------------------------------------------------------------
__global__ __launch_bounds__(256) void prep_x_kernel(const float* __restrict__ x) {
    int i = (blockIdx.x * 256 + threadIdx.x) * 4;
    float4 v = *(const float4*)&x[i];
    uint32_t h0, l0, h1, l1;
    pack_split2h(v.x, v.y, h0, l0);
    pack_split2h(v.z, v.w, h1, l1);
    *(uint32_t*)&g_x_hi[i]     = h0;
    *(uint32_t*)&g_x_hi[i + 2] = h1;
    *(uint32_t*)&g_x_lo[i]     = l0;
    *(uint32_t*)&g_x_lo[i + 2] = l1;
}

// Transpose W [K, N] -> Wt [N, K] fp16 single
__global__ __launch_bounds__(256) void prep_w_kernel(
    const float* __restrict__ W, __half* __restrict__ Wt, int K, int N) {
    __shared__ float tile[32][33];
    int n0 = blockIdx.x * 32, k0 = blockIdx.y * 32;
    int tx = threadIdx.x & 31, ty = threadIdx.x >> 5;   // 32 x 8
    #pragma unroll
    for (int r = 0; r < 32; r += 8)
        tile[ty + r][tx] = W[(size_t)(k0 + ty + r) * N + n0 + tx];
    __syncthreads();
    #pragma unroll
    for (int r = 0; r < 32; r += 8) {
        float v = tile[tx][ty + r];
        Wt[(size_t)(n0 + ty + r) * K + k0 + tx] = __float2half_rn(v);
    }
}

// ---------------------------------------------------------------------------
// mma.sync fp16 A-split 2-term GEMM: D[128x128] = (Ah+Al)[Mx1024] * B^T + bias
// 3-stage cp.async pipeline, BK=32. Packed-swizzled smem (zero padding).
// Stage = 3 arrays x 8KB = 24KB; 3 stages = 72KB; occ 2.
// mode 0: write split bf16 q (x0.125) / k / v head-major.
// mode 1: write fp32 out row-major.
// ---------------------------------------------------------------------------
#define GARR8  8192                 // one array (128x32 fp16 packed)
#define GSTG   (3 * GARR8)          // 24576 per stage
#define GSMEM  (3 * GSTG)           // 73728

// packed smem byte offset for logical row m (0..127), 16B-chunk c (0..3)
__device__ __forceinline__ uint32_t pk_off(int m, int c) {
    return (uint32_t)((m >> 1) * 128 + (m & 1) * 64 + ((c ^ ((m >> 1) & 3)) << 4));
}

__global__ __launch_bounds__(256, 2)
void gemm_f16x2_kernel(const __half* __restrict__ Ah,
                       const __half* __restrict__ Al,
                       const __half* __restrict__ Bw,
                       const float* __restrict__ bias,
                       float* __restrict__ out, int mode) {
    extern __shared__ __align__(16) char dynsm[];

    const int tid  = threadIdx.x;
    const int lane = tid & 31;
    const int wid  = tid >> 5;
    const int wm   = wid & 3;        // warp row: 32 rows each
    const int wn   = wid >> 2;       // warp col: 64 cols each
    const int n0 = blockIdx.x * 128;
    const int m0 = blockIdx.y * 128;

    const uint32_t uS = smem_u32(dynsm);

    float acc[2][8][4] = {};

    auto issue = [&](int ch) {
        const uint32_t sb = uS + (uint32_t)(ch % 3) * GSTG;
        const int k0 = ch * 32;
        #pragma unroll
        for (int it = 0; it < 2; ++it) {
            int idx = tid + it * 256;
            int m = idx >> 2;
            int c = idx & 3;
            uint32_t so = pk_off(m, c);
            size_t ga = (size_t)(m0 + m) * Cdim + k0 + c * 8;
            size_t gb = (size_t)(n0 + m) * Cdim + k0 + c * 8;
            CP_ASYNC16(sb + so,             Ah + ga);
            CP_ASYNC16(sb + GARR8 + so,     Al + ga);
            CP_ASYNC16(sb + 2 * GARR8 + so, Bw + gb);
        }
        CP_COMMIT();
    };

    // per-lane ldmatrix address precomputes (row part + xor key)
    uint32_t arow[2], axor[2], brow[4], bxor[4];
    #pragma unroll
    for (int mt = 0; mt < 2; ++mt) {
        int m = wm * 32 + mt * 16 + (lane & 15);
        arow[mt] = (uint32_t)((m >> 1) * 128 + (m & 1) * 64);
        axor[mt] = (uint32_t)((m >> 1) & 3);
    }
    #pragma unroll
    for (int np = 0; np < 4; ++np) {
        int n = wn * 64 + np * 16 + (lane & 15);
        brow[np] = (uint32_t)((n >> 1) * 128 + (n & 1) * 64);
        bxor[np] = (uint32_t)((n >> 1) & 3);
    }
    const int chalf = lane >> 4;   // which 16B chunk within the k16

    const int NCH = Cdim / 32;   // 32
    issue(0);
    issue(1);

    for (int ch = 0; ch < NCH; ++ch) {
        if (ch + 1 < NCH) { asm volatile("cp.async.wait_group 1;"); }
        else              { asm volatile("cp.async.wait_group 0;"); }
        __syncthreads();
        if (ch + 2 < NCH) issue(ch + 2);

        const uint32_t sb  = uS + (uint32_t)(ch % 3) * GSTG;
        const uint32_t sAh = sb, sAl = sb + GARR8, sB = sb + 2 * GARR8;

        #pragma unroll
        for (int kk = 0; kk < 2; ++kk) {
            const int cix = kk * 2 + chalf;     // chunk index 0..3
            uint32_t ah[8], al[8], bh[16];
            #pragma unroll
            for (int mt = 0; mt < 2; ++mt) {
                uint32_t ao = arow[mt] + (uint32_t)((cix ^ axor[mt]) << 4);
                LDSM4(ah + mt * 4, sAh + ao);
                LDSM4(al + mt * 4, sAl + ao);
            }
            #pragma unroll
            for (int np = 0; np < 4; ++np) {
                uint32_t bo = brow[np] + (uint32_t)((cix ^ bxor[np]) << 4);
                LDSM4(bh + np * 4, sB + bo);
            }
            // pass 1: ah * b (16 distinct accumulators)
            #pragma unroll
            for (int np = 0; np < 4; ++np)
                #pragma unroll
                for (int mt = 0; mt < 2; ++mt)
                    #pragma unroll
                    for (int hf = 0; hf < 2; ++hf)
                        MMA_F16(acc[mt][np * 2 + hf], ah + mt * 4,
                                bh[np * 4 + hf], bh[np * 4 + 2 + hf]);
            // pass 2: al * b
            #pragma unroll
            for (int np = 0; np < 4; ++np)
                #pragma unroll
                for (int mt = 0; mt < 2; ++mt)
                    #pragma unroll
                    for (int hf = 0; hf < 2; ++hf)
                        MMA_F16(acc[mt][np * 2 + hf], al + mt * 4,
                                bh[np * 4 + hf], bh[np * 4 + 2 + hf]);
        }
    }

    // Epilogue
    if (mode == 0) {
        const int ncol0 = n0 + wn * 64;
        const int which = ncol0 >> 10;
        const int hh    = (ncol0 & 1023) >> 6;
        __nv_bfloat16* dh = (which == 0) ? g_qh : ((which == 1) ? g_kh : g_vh);
        __nv_bfloat16* dl = (which == 0) ? g_ql : ((which == 1) ? g_kl : g_vl);
        const float qs = (which == 0) ? 0.125f : 1.0f;
        #pragma unroll
        for (int mt = 0; mt < 2; ++mt) {
            const int rg0 = m0 + wm * 32 + mt * 16 + (lane >> 2);
            const int bb  = rg0 >> 11;
            const int t0  = rg0 & 2047;
            const size_t rbase = (((size_t)bb * Hn + hh) * Tdim + t0) * HDd;
            #pragma unroll
            for (int nt = 0; nt < 8; ++nt) {
                const int d = nt * 8 + (lane & 3) * 2;
                const float2 bv = *(const float2*)&bias[ncol0 + d];
                uint32_t hi, lo;
                pack_split2((acc[mt][nt][0] + bv.x) * qs,
                            (acc[mt][nt][1] + bv.y) * qs, hi, lo);
                *(uint32_t*)&dh[rbase + d] = hi;
                *(uint32_t*)&dl[rbase + d] = lo;
                pack_split2((acc[mt][nt][2] + bv.x) * qs,
                            (acc[mt][nt][3] + bv.y) * qs, hi, lo);
                *(uint32_t*)&dh[rbase + 8 * HDd + d] = hi;
                *(uint32_t*)&dl[rbase + 8 * HDd + d] = lo;
            }
        }
    } else {
        #pragma unroll
        for (int mt = 0; mt < 2; ++mt) {
            const int rg0 = m0 + wm * 32 + mt * 16 + (lane >> 2);
            #pragma unroll
            for (int nt = 0; nt < 8; ++nt) {
                const int ncol = n0 + wn * 64 + nt * 8 + (lane & 3) * 2;
                const float2 bv = *(const float2*)&bias[ncol];
                float2 v0, v1;
                v0.x = acc[mt][nt][0] + bv.x;
                v0.y = acc[mt][nt][1] + bv.y;
                v1.x = acc[mt][nt][2] + bv.x;
                v1.y = acc[mt][nt][3] + bv.y;
                size_t base = (size_t)rg0 * Cdim + ncol;
                *(float2*)&out[base]            = v0;
                *(float2*)&out[base + 8 * Cdim] = v1;
            }
        }
    }
}

// ---------------------------------------------------------------------------
// mma.sync causal flash attention, bf16x3 split for QK^T and PV.
// BQ=128 (8 warps x 16 rows), BKV=64, HD=64. Double-buffered K/V cp.async.
// ---------------------------------------------------------------------------
#define ARS 144                      // row stride bytes
#define AQH 0
#define AQL 18432
#define AKV0 36864
#define KVSTG 36864                  // per-stage block (KH,KL,VH,VL x 9216)
#define ASMEM (AKV0 + 2 * KVSTG)     // 110592

__global__ __launch_bounds__(256, 2) void attn_mma_kernel() {
    extern __shared__ __align__(16) char asmem[];
    const int tid = threadIdx.x;
    const int lane = tid & 31;
    const int w = tid >> 5;
    const int qt = gridDim.x - 1 - blockIdx.x;   // heavy tiles first
    const int bh = blockIdx.y;

    const uint32_t uS = smem_u32(asmem);
    const size_t hbase = (size_t)bh * Tdim * HDd;
    const __nv_bfloat16* qh = g_qh + hbase;
    const __nv_bfloat16* ql = g_ql + hbase;
    const __nv_bfloat16* kh = g_kh + hbase;
    const __nv_bfloat16* kl = g_kl + hbase;
    const __nv_bfloat16* vh = g_vh + hbase;
    const __nv_bfloat16* vl = g_vl + hbase;

    auto issue_kv = [&](int kt) {
        const uint32_t sb = uS + AKV0 + (uint32_t)(kt & 1) * KVSTG;
        #pragma unroll
        for (int it = 0; it < 2; ++it) {
            int idx = tid + it * 256;
            int row = idx >> 3, c = idx & 7;
            uint32_t dst = row * ARS + c * 16;
            size_t src = (size_t)(kt * 64 + row) * HDd + c * 8;
            CP_ASYNC16(sb + dst,         kh + src);
            CP_ASYNC16(sb + 9216 + dst,  kl + src);
            CP_ASYNC16(sb + 18432 + dst, vh + src);
            CP_ASYNC16(sb + 27648 + dst, vl + src);
        }
        CP_COMMIT();
    };

    // Q tile load (committed with KV stage 0)
    #pragma unroll
    for (int it = 0; it < 4; ++it) {
        int idx = tid + it * 256;
        int row = idx >> 3, c = idx & 7;
        uint32_t dst = row * ARS + c * 16;
        size_t src = (size_t)(qt * 128 + row) * HDd + c * 8;
        CP_ASYNC16(uS + AQH + dst, qh + src);
        CP_ASYNC16(uS + AQL + dst, ql + src);
    }
    issue_kv(0);

    const int r4 = lane >> 2;
    const int c2 = (lane & 3) * 2;
    float m0 = -1e30f, m1 = -1e30f, l0 = 0.f, l1 = 0.f;
    float O[8][4] = {};

    const int nkt = 2 * qt + 2;
    for (int kt = 0; kt < nkt; ++kt) {
        const bool more = (kt + 1 < nkt);
        if (more) issue_kv(kt + 1);
        if (more) { asm volatile("cp.async.wait_group 1;"); }
        else      { asm volatile("cp.async.wait_group 0;"); }
        __syncthreads();

        const uint32_t kvb = uS + AKV0 + (uint32_t)(kt & 1) * KVSTG;
        const uint32_t uKH = kvb, uKL = kvb + 9216;
        const uint32_t uVH = kvb + 18432, uVL = kvb + 27648;

        // ---- S = Q K^T (3-term split, term-pass reordered) ----
        float S[8][4] = {};
        #pragma unroll
        for (int k16 = 0; k16 < 4; ++k16) {
            const uint32_t qoff =
                (uint32_t)((w * 16 + (lane & 15)) * ARS + (lane >> 4) * 16 + k16 * 32);
            const uint32_t kfrag =
                (uint32_t)((lane & 15) * ARS + (lane >> 4) * 16 + k16 * 32);
            uint32_t aqh[4], aql[4], bkh[16];
            LDSM4(aqh, uS + AQH + qoff);
            LDSM4(aql, uS + AQL + qoff);
            #pragma unroll
            for (int kp = 0; kp < 4; ++kp)
                LDSM4(bkh + kp * 4, uKH + kfrag + (uint32_t)(kp * 16) * ARS);
            #pragma unroll
            for (int kp = 0; kp < 4; ++kp)
                #pragma unroll
                for (int hf = 0; hf < 2; ++hf)
                    MMA_BF16(S[kp * 2 + hf], aqh, bkh[kp * 4 + hf], bkh[kp * 4 + 2 + hf]);
            #pragma unroll
            for (int kp = 0; kp < 4; ++kp) {
                uint32_t bkl[4];
                LDSM4(bkl, uKL + kfrag + (uint32_t)(kp * 16) * ARS);
                #pragma unroll
                for (int hf = 0; hf < 2; ++hf)
                    MMA_BF16(S[kp * 2 + hf], aqh, bkl[hf], bkl[2 + hf]);
            }
            #pragma unroll
            for (int kp = 0; kp < 4; ++kp)
                #pragma unroll
                for (int hf = 0; hf < 2; ++hf)
                    MMA_BF16(S[kp * 2 + hf], aql, bkh[kp * 4 + hf], bkh[kp * 4 + 2 + hf]);
        }

        // ---- causal mask ----
        const int row0 = qt * 128 + w * 16 + r4;
        if (kt * 64 + 63 > qt * 128 + w * 16) {
            #pragma unroll
            for (int j = 0; j < 8; ++j) {
                const int cb = kt * 64 + j * 8 + c2;
                if (cb     > row0)     S[j][0] = -1e30f;
                if (cb + 1 > row0)     S[j][1] = -1e30f;
                if (cb     > row0 + 8) S[j][2] = -1e30f;
                if (cb + 1 > row0 + 8) S[j][3] = -1e30f;
            }
        }

        // ---- online softmax on fragments ----
        float mt0 = -1e30f, mt1 = -1e30f;
        #pragma unroll
        for (int j = 0; j < 8; ++j) {
            mt0 = fmaxf(mt0, fmaxf(S[j][0], S[j][1]));
            mt1 = fmaxf(mt1, fmaxf(S[j][2], S[j][3]));
        }
        mt0 = fmaxf(mt0, __shfl_xor_sync(0xffffffffu, mt0, 1));
        mt0 = fmaxf(mt0, __shfl_xor_sync(0xffffffffu, mt0, 2));
        mt1 = fmaxf(mt1, __shfl_xor_sync(0xffffffffu, mt1, 1));
        mt1 = fmaxf(mt1, __shfl_xor_sync(0xffffffffu, mt1, 2));
        const float mn0 = fmaxf(m0, mt0);
        const float mn1 = fmaxf(m1, mt1);
        const float sf0 = __expf(m0 - mn0);
        const float sf1 = __expf(m1 - mn1);
        m0 = mn0; m1 = mn1;

        float rs0 = 0.f, rs1 = 0.f;
        #pragma unroll
        for (int j = 0; j < 8; ++j) {
            S[j][0] = __expf(S[j][0] - m0);
            S[j][1] = __expf(S[j][1] - m0);
            S[j][2] = __expf(S[j][2] - m1);
            S[j][3] = __expf(S[j][3] - m1);
            rs0 += S[j][0] + S[j][1];
            rs1 += S[j][2] + S[j][3];
        }
        rs0 += __shfl_xor_sync(0xffffffffu, rs0, 1);
        rs0 += __shfl_xor_sync(0xffffffffu, rs0, 2);
        rs1 += __shfl_xor_sync(0xffffffffu, rs1, 1);
        rs1 += __shfl_xor_sync(0xffffffffu, rs1, 2);
        l0 = l0 * sf0 + rs0;
        l1 = l1 * sf1 + rs1;
        #pragma unroll
        for (int j = 0; j < 8; ++j) {
            O[j][0] *= sf0; O[j][1] *= sf0;
            O[j][2] *= sf1; O[j][3] *= sf1;
        }

        // ---- O += P V (3-term split, term-pass reordered) ----
        #pragma unroll
        for (int s = 0; s < 4; ++s) {
            uint32_t ph[4], pl[4];
            pack_split2(S[2 * s][0],     S[2 * s][1],     ph[0], pl[0]);
            pack_split2(S[2 * s][2],     S[2 * s][3],     ph[1], pl[1]);
            pack_split2(S[2 * s + 1][0], S[2 * s + 1][1], ph[2], pl[2]);
            pack_split2(S[2 * s + 1][2], S[2 * s + 1][3], ph[3], pl[3]);
            const uint32_t vrow =
                (uint32_t)((s * 16 + (lane & 7) + ((lane >> 3) & 1) * 8) * ARS
                           + (lane >> 4) * 16);
            uint32_t bvh[16];
            #pragma unroll
            for (int np = 0; np < 4; ++np)
                LDSM4T(bvh + np * 4, uVH + vrow + np * 32);
            #pragma unroll
            for (int np = 0; np < 4; ++np) {
                MMA_BF16(O[np * 2],     ph, bvh[np * 4],     bvh[np * 4 + 1]);
                MMA_BF16(O[np * 2 + 1], ph, bvh[np * 4 + 2], bvh[np * 4 + 3]);
            }
            #pragma unroll
            for (int np = 0; np < 4; ++np) {
                uint32_t bvl[4];
                LDSM4T(bvl, uVL + vrow + np * 32);
                MMA_BF16(O[np * 2],     ph, bvl[0], bvl[1]);
                MMA_BF16(O[np * 2 + 1], ph, bvl[2], bvl[3]);
            }
            #pragma unroll
            for (int np = 0; np < 4; ++np) {
                MMA_BF16(O[np * 2],     pl, bvh[np * 4],     bvh[np * 4 + 1]);
                MMA_BF16(O[np * 2 + 1], pl, bvh[np * 4 + 2], bvh[np * 4 + 3]);
            }
        }
        __syncthreads();
    }

    // ---- normalize + write split y (fp16 hi/lo for proj) ----
    const float inv0 = 1.f / l0, inv1 = 1.f / l1;
    const int b = bh >> 4, h = bh & 15;
    const int rg0 = b * Tdim + qt * 128 + w * 16 + r4;
    const size_t base0 = (size_t)rg0 * Cdim + h * HDd;
    #pragma unroll
    for (int j = 0; j < 8; ++j) {
        const int d = j * 8 + c2;
        uint32_t hi, lo;
        pack_split2h(O[j][0] * inv0, O[j][1] * inv0, hi, lo);
        *(uint32_t*)&g_y_hi[base0 + d] = hi;
        *(uint32_t*)&g_y_lo[base0 + d] = lo;
        pack_split2h(O[j][2] * inv1, O[j][3] * inv1, hi, lo);
        *(uint32_t*)&g_y_hi[base0 + 8 * Cdim + d] = hi;
        *(uint32_t*)&g_y_lo[base0 + 8 * Cdim + d] = lo;
    }
}

// ---------------------------------------------------------------------------
extern "C" void kernel_launch(void* const* d_in, const int* in_sizes, int n_in,
                              void* d_out, int out_size) {
    const float* x      = (const float*)d_in[0];
    const float* w_attn = (const float*)d_in[1];
    const float* b_attn = (const float*)d_in[2];
    const float* w_proj = (const float*)d_in[3];
    const float* b_proj = (const float*)d_in[4];
    float* out = (float*)d_out;

    static bool attr_set = false;
    if (!attr_set) {
        cudaFuncSetAttribute(gemm_f16x2_kernel,
                             cudaFuncAttributeMaxDynamicSharedMemorySize, GSMEM);
        cudaFuncSetAttribute(attn_mma_kernel,
                             cudaFuncAttributeMaxDynamicSharedMemorySize, ASMEM);
        attr_set = true;
    }

    __half *x_hi, *x_lo, *wa, *wp, *y_hi, *y_lo;
    cudaGetSymbolAddress((void**)&x_hi, g_x_hi);
    cudaGetSymbolAddress((void**)&x_lo, g_x_lo);
    cudaGetSymbolAddress((void**)&wa, g_wa);
    cudaGetSymbolAddress((void**)&wp, g_wp);
    cudaGetSymbolAddress((void**)&y_hi, g_y_hi);
    cudaGetSymbolAddress((void**)&y_lo, g_y_lo);

    // Prep: split x (fp16 hi/lo), transpose weights (fp16 single)
    prep_x_kernel<<<Mrows * Cdim / (256 * 4), 256>>>(x);
    {
        dim3 ga(N3 / 32, Cdim / 32);
        prep_w_kernel<<<ga, 256>>>(w_attn, wa, Cdim, N3);
        dim3 gp(Cdim / 32, Cdim / 32);
        prep_w_kernel<<<gp, 256>>>(w_proj, wp, Cdim, Cdim);
    }

    // QKV GEMM -> split q/k/v head-major (bf16 for attention)
    dim3 g1(N3 / 128, Mrows / 128);     // 24 x 32
    gemm_f16x2_kernel<<<g1, 256, GSMEM>>>(x_hi, x_lo, wa, b_attn, nullptr, 0);

    // Attention (tensor-core, bf16x3, double-buffered K/V)
    dim3 g2(Tdim / 128, Bdim * Hn);     // 16 x 32
    attn_mma_kernel<<<g2, 256, ASMEM>>>();

    // Proj GEMM
    dim3 g3(Cdim / 128, Mrows / 128);   // 8 x 32
    gemm_f16x2_kernel<<<g3, 256, GSMEM>>>(y_hi, y_lo, wp, b_proj, out, 1);
}

// round 8
// speedup vs baseline: 4.0064x; 1.1735x over previous
#include <cuda_runtime.h>
#include <cuda_bf16.h>
#include <cuda_fp16.h>
#include <cstdint>

// Problem constants
#define Bdim 2
#define Tdim 2048
#define Cdim 1024
#define Hn   16
#define HDd  64
#define Mrows (Bdim * Tdim)   // 4096
#define N3    (3 * Cdim)      // 3072

// ---------------------------------------------------------------------------
// Scratch (__device__ globals; allocation-free rule)
// ---------------------------------------------------------------------------
__device__ __half g_x_hi[Mrows * Cdim];
__device__ __half g_x_lo[Mrows * Cdim];
__device__ __half g_wa[N3 * Cdim];        // [N=3072][K=1024], fp16 single
__device__ __half g_wp[Cdim * Cdim];      // [N=1024][K=1024], fp16 single
__device__ __half g_y_hi[Mrows * Cdim];   // attn output, [B*T][C], fp16 split
__device__ __half g_y_lo[Mrows * Cdim];

// q split fp16 (pre-scaled by 1/8); k, v single fp16. Head-major [B*H][T][HD]
__device__ __half g_qh[Bdim * Hn * Tdim * HDd];
__device__ __half g_ql[Bdim * Hn * Tdim * HDd];
__device__ __half g_k [Bdim * Hn * Tdim * HDd];
__device__ __half g_v [Bdim * Hn * Tdim * HDd];

// ---------------------------------------------------------------------------
// PTX helpers (plain sm_103-safe)
// ---------------------------------------------------------------------------
__device__ __forceinline__ uint32_t smem_u32(const void* p) {
    uint32_t a;
    asm("{ .reg .u64 t; cvta.to.shared.u64 t, %1; cvt.u32.u64 %0, t; }"
        : "=r"(a) : "l"(p));
    return a;
}

#define LDSM4(r, addr) \
    asm volatile("ldmatrix.sync.aligned.m8n8.x4.shared.b16 {%0,%1,%2,%3}, [%4];" \
        : "=r"((r)[0]), "=r"((r)[1]), "=r"((r)[2]), "=r"((r)[3]) : "r"(addr))

#define LDSM4T(r, addr) \
    asm volatile("ldmatrix.sync.aligned.m8n8.x4.trans.shared.b16 {%0,%1,%2,%3}, [%4];" \
        : "=r"((r)[0]), "=r"((r)[1]), "=r"((r)[2]), "=r"((r)[3]) : "r"(addr))

#define MMA_F16(c, a, b0, b1) \
    asm volatile("mma.sync.aligned.m16n8k16.row.col.f32.f16.f16.f32 " \
        "{%0,%1,%2,%3}, {%4,%5,%6,%7}, {%8,%9}, {%0,%1,%2,%3};" \
        : "+f"((c)[0]), "+f"((c)[1]), "+f"((c)[2]), "+f"((c)[3]) \
        : "r"((a)[0]), "r"((a)[1]), "r"((a)[2]), "r"((a)[3]), "r"(b0), "r"(b1))

#define CP_ASYNC16(dst, src) \
    asm volatile("cp.async.cg.shared.global [%0], [%1], 16;" :: "r"(dst), "l"(src))
#define CP_COMMIT() asm volatile("cp.async.commit_group;")

// fp16 split pack
__device__ __forceinline__ void pack_split2h(float v0, float v1,
                                             uint32_t& hi, uint32_t& lo) {
    __half h0 = __float2half_rn(v0);
    __half l0 = __float2half_rn(v0 - __half2float(h0));
    __half h1 = __float2half_rn(v1);
    __half l1 = __float2half_rn(v1 - __half2float(h1));
    __half2 hh(h0, h1), ll(l0, l1);
    hi = *(uint32_t*)&hh;
    lo = *(uint32_t*)&ll;
}

__device__ __forceinline__ uint32_t pack2h(float v0, float v1) {
    __half2 h(__float2half_rn(v0), __float2half_rn(v1));
    return *(uint32_t*)&h;
}

// ---------------------------------------------------------------------------
// Prep kernels
// ---------------------------------------------------------------------------
__global__ __launch_bounds__(256) void prep_x_kernel(const float* __restrict__ x) {
    int i = (blockIdx.x * 256 + threadIdx.x) * 4;
    float4 v = *(const float4*)&x[i];
    uint32_t h0, l0, h1, l1;
    pack_split2h(v.x, v.y, h0, l0);
    pack_split2h(v.z, v.w, h1, l1);
    *(uint32_t*)&g_x_hi[i]     = h0;
    *(uint32_t*)&g_x_hi[i + 2] = h1;
    *(uint32_t*)&g_x_lo[i]     = l0;
    *(uint32_t*)&g_x_lo[i + 2] = l1;
}

// Transpose W [K, N] -> Wt [N, K] fp16 single
__global__ __launch_bounds__(256) void prep_w_kernel(
    const float* __restrict__ W, __half* __restrict__ Wt, int K, int N) {
    __shared__ float tile[32][33];
    int n0 = blockIdx.x * 32, k0 = blockIdx.y * 32;
    int tx = threadIdx.x & 31, ty = threadIdx.x >> 5;   // 32 x 8
    #pragma unroll
    for (int r = 0; r < 32; r += 8)
        tile[ty + r][tx] = W[(size_t)(k0 + ty + r) * N + n0 + tx];
    __syncthreads();
    #pragma unroll
    for (int r = 0; r < 32; r += 8) {
        float v = tile[tx][ty + r];
        Wt[(size_t)(n0 + ty + r) * K + k0 + tx] = __float2half_rn(v);
    }
}

// ---------------------------------------------------------------------------
// mma.sync fp16 A-split 2-term GEMM: D[128x128] = (Ah+Al)[Mx1024] * B^T + bias
// 3-stage cp.async pipeline, BK=32. Packed-swizzled smem (zero padding).
// mode 0: write q fp16-split (x0.125) / k,v fp16-single head-major.
// mode 1: write fp32 out row-major.
// ---------------------------------------------------------------------------
#define GARR8  8192                 // one array (128x32 fp16 packed)
#define GSTG   (3 * GARR8)          // 24576 per stage
#define GSMEM  (3 * GSTG)           // 73728

// packed smem byte offset for logical row m (0..127), 16B-chunk c (0..3)
__device__ __forceinline__ uint32_t pk_off(int m, int c) {
    return (uint32_t)((m >> 1) * 128 + (m & 1) * 64 + ((c ^ ((m >> 1) & 3)) << 4));
}

__global__ __launch_bounds__(256, 2)
void gemm_f16x2_kernel(const __half* __restrict__ Ah,
                       const __half* __restrict__ Al,
                       const __half* __restrict__ Bw,
                       const float* __restrict__ bias,
                       float* __restrict__ out, int mode) {
    extern __shared__ __align__(16) char dynsm[];

    const int tid  = threadIdx.x;
    const int lane = tid & 31;
    const int wid  = tid >> 5;
    const int wm   = wid & 3;        // warp row: 32 rows each
    const int wn   = wid >> 2;       // warp col: 64 cols each
    const int n0 = blockIdx.x * 128;
    const int m0 = blockIdx.y * 128;

    const uint32_t uS = smem_u32(dynsm);

    float acc[2][8][4] = {};

    auto issue = [&](int ch) {
        const uint32_t sb = uS + (uint32_t)(ch % 3) * GSTG;
        const int k0 = ch * 32;
        #pragma unroll
        for (int it = 0; it < 2; ++it) {
            int idx = tid + it * 256;
            int m = idx >> 2;
            int c = idx & 3;
            uint32_t so = pk_off(m, c);
            size_t ga = (size_t)(m0 + m) * Cdim + k0 + c * 8;
            size_t gb = (size_t)(n0 + m) * Cdim + k0 + c * 8;
            CP_ASYNC16(sb + so,             Ah + ga);
            CP_ASYNC16(sb + GARR8 + so,     Al + ga);
            CP_ASYNC16(sb + 2 * GARR8 + so, Bw + gb);
        }
        CP_COMMIT();
    };

    // per-lane ldmatrix address precomputes (row part + xor key)
    uint32_t arow[2], axor[2], brow[4], bxor[4];
    #pragma unroll
    for (int mt = 0; mt < 2; ++mt) {
        int m = wm * 32 + mt * 16 + (lane & 15);
        arow[mt] = (uint32_t)((m >> 1) * 128 + (m & 1) * 64);
        axor[mt] = (uint32_t)((m >> 1) & 3);
    }
    #pragma unroll
    for (int np = 0; np < 4; ++np) {
        int n = wn * 64 + np * 16 + (lane & 15);
        brow[np] = (uint32_t)((n >> 1) * 128 + (n & 1) * 64);
        bxor[np] = (uint32_t)((n >> 1) & 3);
    }
    const int chalf = lane >> 4;   // which 16B chunk within the k16

    const int NCH = Cdim / 32;   // 32
    issue(0);
    issue(1);

    for (int ch = 0; ch < NCH; ++ch) {
        if (ch + 1 < NCH) { asm volatile("cp.async.wait_group 1;"); }
        else              { asm volatile("cp.async.wait_group 0;"); }
        __syncthreads();
        if (ch + 2 < NCH) issue(ch + 2);

        const uint32_t sb  = uS + (uint32_t)(ch % 3) * GSTG;
        const uint32_t sAh = sb, sAl = sb + GARR8, sB = sb + 2 * GARR8;

        #pragma unroll
        for (int kk = 0; kk < 2; ++kk) {
            const int cix = kk * 2 + chalf;     // chunk index 0..3
            uint32_t ah[8], al[8], bh[16];
            #pragma unroll
            for (int mt = 0; mt < 2; ++mt) {
                uint32_t ao = arow[mt] + (uint32_t)((cix ^ axor[mt]) << 4);
                LDSM4(ah + mt * 4, sAh + ao);
                LDSM4(al + mt * 4, sAl + ao);
            }
            #pragma unroll
            for (int np = 0; np < 4; ++np) {
                uint32_t bo = brow[np] + (uint32_t)((cix ^ bxor[np]) << 4);
                LDSM4(bh + np * 4, sB + bo);
            }
            // pass 1: ah * b (16 distinct accumulators)
            #pragma unroll
            for (int np = 0; np < 4; ++np)
                #pragma unroll
                for (int mt = 0; mt < 2; ++mt)
                    #pragma unroll
                    for (int hf = 0; hf < 2; ++hf)
                        MMA_F16(acc[mt][np * 2 + hf], ah + mt * 4,
                                bh[np * 4 + hf], bh[np * 4 + 2 + hf]);
            // pass 2: al * b
            #pragma unroll
            for (int np = 0; np < 4; ++np)
                #pragma unroll
                for (int mt = 0; mt < 2; ++mt)
                    #pragma unroll
                    for (int hf = 0; hf < 2; ++hf)
                        MMA_F16(acc[mt][np * 2 + hf], al + mt * 4,
                                bh[np * 4 + hf], bh[np * 4 + 2 + hf]);
        }
    }

    // Epilogue
    if (mode == 0) {
        const int ncol0 = n0 + wn * 64;
        const int which = ncol0 >> 10;
        const int hh    = (ncol0 & 1023) >> 6;
        #pragma unroll
        for (int mt = 0; mt < 2; ++mt) {
            const int rg0 = m0 + wm * 32 + mt * 16 + (lane >> 2);
            const int bb  = rg0 >> 11;
            const int t0  = rg0 & 2047;
            const size_t rbase = (((size_t)bb * Hn + hh) * Tdim + t0) * HDd;
            #pragma unroll
            for (int nt = 0; nt < 8; ++nt) {
                const int d = nt * 8 + (lane & 3) * 2;
                const float2 bv = *(const float2*)&bias[ncol0 + d];
                float v00 = acc[mt][nt][0] + bv.x;
                float v01 = acc[mt][nt][1] + bv.y;
                float v10 = acc[mt][nt][2] + bv.x;
                float v11 = acc[mt][nt][3] + bv.y;
                if (which == 0) {
                    uint32_t hi, lo;
                    pack_split2h(v00 * 0.125f, v01 * 0.125f, hi, lo);
                    *(uint32_t*)&g_qh[rbase + d] = hi;
                    *(uint32_t*)&g_ql[rbase + d] = lo;
                    pack_split2h(v10 * 0.125f, v11 * 0.125f, hi, lo);
                    *(uint32_t*)&g_qh[rbase + 8 * HDd + d] = hi;
                    *(uint32_t*)&g_ql[rbase + 8 * HDd + d] = lo;
                } else {
                    __half* dst = (which == 1) ? g_k : g_v;
                    *(uint32_t*)&dst[rbase + d]           = pack2h(v00, v01);
                    *(uint32_t*)&dst[rbase + 8 * HDd + d] = pack2h(v10, v11);
                }
            }
        }
    } else {
        #pragma unroll
        for (int mt = 0; mt < 2; ++mt) {
            const int rg0 = m0 + wm * 32 + mt * 16 + (lane >> 2);
            #pragma unroll
            for (int nt = 0; nt < 8; ++nt) {
                const int ncol = n0 + wn * 64 + nt * 8 + (lane & 3) * 2;
                const float2 bv = *(const float2*)&bias[ncol];
                float2 v0, v1;
                v0.x = acc[mt][nt][0] + bv.x;
                v0.y = acc[mt][nt][1] + bv.y;
                v1.x = acc[mt][nt][2] + bv.x;
                v1.y = acc[mt][nt][3] + bv.y;
                size_t base = (size_t)rg0 * Cdim + ncol;
                *(float2*)&out[base]            = v0;
                *(float2*)&out[base + 8 * Cdim] = v1;
            }
        }
    }
}

// ---------------------------------------------------------------------------
// mma.sync causal flash attention, fp16 A-split 2-term for QK^T and PV.
// BQ=128 (8 warps x 16 rows), BKV=64, HD=64. Double-buffered K/V cp.async.
// smem: Q hi/lo @ 0/18432; stage s: K @ 36864+s*18432, V @ +9216.
// ---------------------------------------------------------------------------
#define ARS 144                      // row stride bytes
#define AQH 0
#define AQL 18432
#define AKV0 36864
#define KVSTG 18432                  // per-stage (K 9216 + V 9216)
#define ASMEM (AKV0 + 2 * KVSTG)     // 73728

__global__ __launch_bounds__(256, 2) void attn_mma_kernel() {
    extern __shared__ __align__(16) char asmem[];
    const int tid = threadIdx.x;
    const int lane = tid & 31;
    const int w = tid >> 5;
    const int qt = gridDim.x - 1 - blockIdx.x;   // heavy tiles first
    const int bh = blockIdx.y;

    const uint32_t uS = smem_u32(asmem);
    const size_t hbase = (size_t)bh * Tdim * HDd;
    const __half* qh = g_qh + hbase;
    const __half* ql = g_ql + hbase;
    const __half* kk = g_k + hbase;
    const __half* vv = g_v + hbase;

    auto issue_kv = [&](int kt) {
        const uint32_t sb = uS + AKV0 + (uint32_t)(kt & 1) * KVSTG;
        #pragma unroll
        for (int it = 0; it < 2; ++it) {
            int idx = tid + it * 256;
            int row = idx >> 3, c = idx & 7;
            uint32_t dst = row * ARS + c * 16;
            size_t src = (size_t)(kt * 64 + row) * HDd + c * 8;
            CP_ASYNC16(sb + dst,        kk + src);
            CP_ASYNC16(sb + 9216 + dst, vv + src);
        }
        CP_COMMIT();
    };

    // Q tile load (committed with KV stage 0)
    #pragma unroll
    for (int it = 0; it < 4; ++it) {
        int idx = tid + it * 256;
        int row = idx >> 3, c = idx & 7;
        uint32_t dst = row * ARS + c * 16;
        size_t src = (size_t)(qt * 128 + row) * HDd + c * 8;
        CP_ASYNC16(uS + AQH + dst, qh + src);
        CP_ASYNC16(uS + AQL + dst, ql + src);
    }
    issue_kv(0);

    const int r4 = lane >> 2;
    const int c2 = (lane & 3) * 2;
    float m0 = -1e30f, m1 = -1e30f, l0 = 0.f, l1 = 0.f;
    float O[8][4] = {};

    const int nkt = 2 * qt + 2;
    for (int kt = 0; kt < nkt; ++kt) {
        const bool more = (kt + 1 < nkt);
        if (more) issue_kv(kt + 1);
        if (more) { asm volatile("cp.async.wait_group 1;"); }
        else      { asm volatile("cp.async.wait_group 0;"); }
        __syncthreads();

        const uint32_t kvb = uS + AKV0 + (uint32_t)(kt & 1) * KVSTG;
        const uint32_t uK = kvb, uV = kvb + 9216;

        // ---- S = Q K^T (2-term fp16 split) ----
        float S[8][4] = {};
        #pragma unroll
        for (int k16 = 0; k16 < 4; ++k16) {
            const uint32_t qoff =
                (uint32_t)((w * 16 + (lane & 15)) * ARS + (lane >> 4) * 16 + k16 * 32);
            const uint32_t kfrag =
                (uint32_t)((lane & 15) * ARS + (lane >> 4) * 16 + k16 * 32);
            uint32_t aqh[4], aql[4], bk[16];
            LDSM4(aqh, uS + AQH + qoff);
            LDSM4(aql, uS + AQL + qoff);
            #pragma unroll
            for (int kp = 0; kp < 4; ++kp)
                LDSM4(bk + kp * 4, uK + kfrag + (uint32_t)(kp * 16) * ARS);
            // pass 1: qh*k (8 distinct accs)
            #pragma unroll
            for (int kp = 0; kp < 4; ++kp)
                #pragma unroll
                for (int hf = 0; hf < 2; ++hf)
                    MMA_F16(S[kp * 2 + hf], aqh, bk[kp * 4 + hf], bk[kp * 4 + 2 + hf]);
            // pass 2: ql*k
            #pragma unroll
            for (int kp = 0; kp < 4; ++kp)
                #pragma unroll
                for (int hf = 0; hf < 2; ++hf)
                    MMA_F16(S[kp * 2 + hf], aql, bk[kp * 4 + hf], bk[kp * 4 + 2 + hf]);
        }

        // ---- causal mask ----
        const int row0 = qt * 128 + w * 16 + r4;
        if (kt * 64 + 63 > qt * 128 + w * 16) {
            #pragma unroll
            for (int j = 0; j < 8; ++j) {
                const int cb = kt * 64 + j * 8 + c2;
                if (cb     > row0)     S[j][0] = -1e30f;
                if (cb + 1 > row0)     S[j][1] = -1e30f;
                if (cb     > row0 + 8) S[j][2] = -1e30f;
                if (cb + 1 > row0 + 8) S[j][3] = -1e30f;
            }
        }

        // ---- online softmax on fragments ----
        float mt0 = -1e30f, mt1 = -1e30f;
        #pragma unroll
        for (int j = 0; j < 8; ++j) {
            mt0 = fmaxf(mt0, fmaxf(S[j][0], S[j][1]));
            mt1 = fmaxf(mt1, fmaxf(S[j][2], S[j][3]));
        }
        mt0 = fmaxf(mt0, __shfl_xor_sync(0xffffffffu, mt0, 1));
        mt0 = fmaxf(mt0, __shfl_xor_sync(0xffffffffu, mt0, 2));
        mt1 = fmaxf(mt1, __shfl_xor_sync(0xffffffffu, mt1, 1));
        mt1 = fmaxf(mt1, __shfl_xor_sync(0xffffffffu, mt1, 2));
        const float mn0 = fmaxf(m0, mt0);
        const float mn1 = fmaxf(m1, mt1);
        const float sf0 = __expf(m0 - mn0);
        const float sf1 = __expf(m1 - mn1);
        m0 = mn0; m1 = mn1;

        float rs0 = 0.f, rs1 = 0.f;
        #pragma unroll
        for (int j = 0; j < 8; ++j) {
            S[j][0] = __expf(S[j][0] - m0);
            S[j][1] = __expf(S[j][1] - m0);
            S[j][2] = __expf(S[j][2] - m1);
            S[j][3] = __expf(S[j][3] - m1);
            rs0 += S[j][0] + S[j][1];
            rs1 += S[j][2] + S[j][3];
        }
        rs0 += __shfl_xor_sync(0xffffffffu, rs0, 1);
        rs0 += __shfl_xor_sync(0xffffffffu, rs0, 2);
        rs1 += __shfl_xor_sync(0xffffffffu, rs1, 1);
        rs1 += __shfl_xor_sync(0xffffffffu, rs1, 2);
        l0 = l0 * sf0 + rs0;
        l1 = l1 * sf1 + rs1;
        #pragma unroll
        for (int j = 0; j < 8; ++j) {
            O[j][0] *= sf0; O[j][1] *= sf0;
            O[j][2] *= sf1; O[j][3] *= sf1;
        }

        // ---- O += P V (2-term fp16 split P, single V) ----
        #pragma unroll
        for (int s = 0; s < 4; ++s) {
            uint32_t ph[4], pl[4];
            pack_split2h(S[2 * s][0],     S[2 * s][1],     ph[0], pl[0]);
            pack_split2h(S[2 * s][2],     S[2 * s][3],     ph[1], pl[1]);
            pack_split2h(S[2 * s + 1][0], S[2 * s + 1][1], ph[2], pl[2]);
            pack_split2h(S[2 * s + 1][2], S[2 * s + 1][3], ph[3], pl[3]);
            const uint32_t vrow =
                (uint32_t)((s * 16 + (lane & 7) + ((lane >> 3) & 1) * 8) * ARS
                           + (lane >> 4) * 16);
            uint32_t bv[16];
            #pragma unroll
            for (int np = 0; np < 4; ++np)
                LDSM4T(bv + np * 4, uV + vrow + np * 32);
            // pass 1: ph*v (8 distinct accs)
            #pragma unroll
            for (int np = 0; np < 4; ++np) {
                MMA_F16(O[np * 2],     ph, bv[np * 4],     bv[np * 4 + 1]);
                MMA_F16(O[np * 2 + 1], ph, bv[np * 4 + 2], bv[np * 4 + 3]);
            }
            // pass 2: pl*v
            #pragma unroll
            for (int np = 0; np < 4; ++np) {
                MMA_F16(O[np * 2],     pl, bv[np * 4],     bv[np * 4 + 1]);
                MMA_F16(O[np * 2 + 1], pl, bv[np * 4 + 2], bv[np * 4 + 3]);
            }
        }
        __syncthreads();
    }

    // ---- normalize + write split y (fp16 hi/lo for proj) ----
    const float inv0 = 1.f / l0, inv1 = 1.f / l1;
    const int b = bh >> 4, h = bh & 15;
    const int rg0 = b * Tdim + qt * 128 + w * 16 + r4;
    const size_t base0 = (size_t)rg0 * Cdim + h * HDd;
    #pragma unroll
    for (int j = 0; j < 8; ++j) {
        const int d = j * 8 + c2;
        uint32_t hi, lo;
        pack_split2h(O[j][0] * inv0, O[j][1] * inv0, hi, lo);
        *(uint32_t*)&g_y_hi[base0 + d] = hi;
        *(uint32_t*)&g_y_lo[base0 + d] = lo;
        pack_split2h(O[j][2] * inv1, O[j][3] * inv1, hi, lo);
        *(uint32_t*)&g_y_hi[base0 + 8 * Cdim + d] = hi;
        *(uint32_t*)&g_y_lo[base0 + 8 * Cdim + d] = lo;
    }
}

// ---------------------------------------------------------------------------
extern "C" void kernel_launch(void* const* d_in, const int* in_sizes, int n_in,
                              void* d_out, int out_size) {
    const float* x      = (const float*)d_in[0];
    const float* w_attn = (const float*)d_in[1];
    const float* b_attn = (const float*)d_in[2];
    const float* w_proj = (const float*)d_in[3];
    const float* b_proj = (const float*)d_in[4];
    float* out = (float*)d_out;

    static bool attr_set = false;
    if (!attr_set) {
        cudaFuncSetAttribute(gemm_f16x2_kernel,
                             cudaFuncAttributeMaxDynamicSharedMemorySize, GSMEM);
        cudaFuncSetAttribute(attn_mma_kernel,
                             cudaFuncAttributeMaxDynamicSharedMemorySize, ASMEM);
        attr_set = true;
    }

    __half *x_hi, *x_lo, *wa, *wp, *y_hi, *y_lo;
    cudaGetSymbolAddress((void**)&x_hi, g_x_hi);
    cudaGetSymbolAddress((void**)&x_lo, g_x_lo);
    cudaGetSymbolAddress((void**)&wa, g_wa);
    cudaGetSymbolAddress((void**)&wp, g_wp);
    cudaGetSymbolAddress((void**)&y_hi, g_y_hi);
    cudaGetSymbolAddress((void**)&y_lo, g_y_lo);

    // Prep: split x (fp16 hi/lo), transpose weights (fp16 single)
    prep_x_kernel<<<Mrows * Cdim / (256 * 4), 256>>>(x);
    {
        dim3 ga(N3 / 32, Cdim / 32);
        prep_w_kernel<<<ga, 256>>>(w_attn, wa, Cdim, N3);
        dim3 gp(Cdim / 32, Cdim / 32);
        prep_w_kernel<<<gp, 256>>>(w_proj, wp, Cdim, Cdim);
    }

    // QKV GEMM -> q fp16-split / k,v fp16-single head-major
    dim3 g1(N3 / 128, Mrows / 128);     // 24 x 32
    gemm_f16x2_kernel<<<g1, 256, GSMEM>>>(x_hi, x_lo, wa, b_attn, nullptr, 0);

    // Attention (tensor-core, fp16 2-term, double-buffered K/V)
    dim3 g2(Tdim / 128, Bdim * Hn);     // 16 x 32
    attn_mma_kernel<<<g2, 256, ASMEM>>>();

    // Proj GEMM
    dim3 g3(Cdim / 128, Mrows / 128);   // 8 x 32
    gemm_f16x2_kernel<<<g3, 256, GSMEM>>>(y_hi, y_lo, wp, b_proj, out, 1);
}